// round 8
// baseline (speedup 1.0000x reference)
#include <cuda_runtime.h>
#include <cuda_bf16.h>
#include <cstdint>

typedef __nv_bfloat16 bf16;

// ---------------------------------------------------------------------------
static __device__ __forceinline__ uint32_t smem_u32(const void* p) {
    uint32_t a;
    asm("{ .reg .u64 t; cvta.to.shared.u64 t, %1; cvt.u32.u64 %0, t; }" : "=r"(a) : "l"(p));
    return a;
}
static __device__ __forceinline__ void mma16816(float* c, const uint32_t* a, const uint32_t* b) {
    asm volatile("mma.sync.aligned.m16n8k16.row.col.f32.bf16.bf16.f32 "
        "{%0,%1,%2,%3}, {%4,%5,%6,%7}, {%8,%9}, {%0,%1,%2,%3};"
        : "+f"(c[0]), "+f"(c[1]), "+f"(c[2]), "+f"(c[3])
        : "r"(a[0]), "r"(a[1]), "r"(a[2]), "r"(a[3]), "r"(b[0]), "r"(b[1]));
}
static __device__ __forceinline__ void mma3(float* c, const uint32_t* ah, const uint32_t* al,
                                            const uint32_t* bh, const uint32_t* bl) {
    mma16816(c, ah, bh); mma16816(c, ah, bl); mma16816(c, al, bh);
}
static __device__ __forceinline__ void ldsm4(uint32_t* r, uint32_t a) {
    asm volatile("ldmatrix.sync.aligned.m8n8.x4.shared.b16 {%0,%1,%2,%3}, [%4];"
        : "=r"(r[0]), "=r"(r[1]), "=r"(r[2]), "=r"(r[3]) : "r"(a));
}
static __device__ __forceinline__ void ldsmA(uint32_t* r, uint32_t base, int m0, int k0, int sbytes, int lane) {
    ldsm4(r, base + (uint32_t)((m0 + (lane & 7) + ((lane >> 3) & 1) * 8) * sbytes
                               + (k0 + ((lane >> 4) << 3)) * 2));
}
static __device__ __forceinline__ void ldsmB(uint32_t* r, uint32_t base, int n0, int k0, int sbytes, int lane) {
    ldsm4(r, base + (uint32_t)((n0 + (lane & 7) + ((lane >> 4) << 3)) * sbytes
                               + (k0 + (((lane >> 3) & 1) << 3)) * 2));
}
#define CP16(sm_, gp_) asm volatile("cp.async.cg.shared.global [%0], [%1], 16;" :: "r"(sm_), "l"(gp_))
#define CPCOMMIT()     asm volatile("cp.async.commit_group;")
#define CPWAIT(n)      asm volatile("cp.async.wait_group %0;" :: "n"(n))

static __device__ __forceinline__ void store_split2(bf16* Ch, bf16* Cl, long off, float x, float y) {
    __align__(4) bf16 h[2] = {__float2bfloat16(x), __float2bfloat16(y)};
    __align__(4) bf16 l[2] = {__float2bfloat16(x - __bfloat162float(h[0])),
                              __float2bfloat16(y - __bfloat162float(h[1]))};
    *(uint32_t*)(Ch + off) = *(uint32_t*)h;
    *(uint32_t*)(Cl + off) = *(uint32_t*)l;
}
static __device__ __forceinline__ void smem_split2(char* ph, char* pl, float x, float y) {
    __align__(4) bf16 h[2] = {__float2bfloat16(x), __float2bfloat16(y)};
    __align__(4) bf16 l[2] = {__float2bfloat16(x - __bfloat162float(h[0])),
                              __float2bfloat16(y - __bfloat162float(h[1]))};
    *(uint32_t*)ph = *(uint32_t*)h;
    *(uint32_t*)pl = *(uint32_t*)l;
}

// ---------------- scratch ----------------
__device__ bf16 g_qh[4194304], g_ql[4194304];
__device__ bf16 g_xh[4194304], g_xl[4194304];
__device__ bf16 g_wqh[1048576], g_wql[1048576];
__device__ bf16 g_wkh[1048576], g_wkl[1048576];
__device__ bf16 g_wvh[1048576], g_wvl[1048576];
__device__ bf16 g_woh[1048576], g_wol[1048576];
__device__ bf16 g_Qh[4194304], g_Ql[4194304];
__device__ bf16 g_Kh[4194304], g_Kl[4194304];
__device__ bf16 g_Vh[4194304], g_Vl[4194304];
__device__ bf16 g_Vth[4194304], g_Vtl[4194304];  // [bh][64 d][2048 tok]
__device__ bf16 g_Bh[4194304], g_Bl[4194304];
__device__ float g_attn[134217728];

// ---------------- merged fp32 -> bf16 hi/lo for all 6 tensors ----------------
__global__ __launch_bounds__(256) void cvt_all(
    const float* __restrict__ s0, const float* __restrict__ s1,
    const float* __restrict__ s2, const float* __restrict__ s3,
    const float* __restrict__ s4, const float* __restrict__ s5,
    bf16* __restrict__ h0, bf16* __restrict__ l0, bf16* __restrict__ h1, bf16* __restrict__ l1,
    bf16* __restrict__ h2, bf16* __restrict__ l2, bf16* __restrict__ h3, bf16* __restrict__ l3,
    bf16* __restrict__ h4, bf16* __restrict__ l4, bf16* __restrict__ h5, bf16* __restrict__ l5)
{
    long i = (long)blockIdx.x * 256 + threadIdx.x;   // < 3145728
    const float* src; bf16 *h, *l; long li;
    if (i < 1048576)      { src = s0; h = h0; l = l0; li = i; }
    else if (i < 2097152) { src = s1; h = h1; l = l1; li = i - 1048576; }
    else {
        long j = i - 2097152;
        int w = (int)(j >> 18);
        li = j & 262143;
        src = (w == 0) ? s2 : (w == 1) ? s3 : (w == 2) ? s4 : s5;
        h   = (w == 0) ? h2 : (w == 1) ? h3 : (w == 2) ? h4 : h5;
        l   = (w == 0) ? l2 : (w == 1) ? l3 : (w == 2) ? l4 : l5;
    }
    float4 v = ((const float4*)src)[li];
    float f[4] = {v.x, v.y, v.z, v.w};
    __align__(8) bf16 hv[4], lv[4];
#pragma unroll
    for (int j = 0; j < 4; j++) {
        hv[j] = __float2bfloat16(f[j]);
        lv[j] = __float2bfloat16(f[j] - __bfloat162float(hv[j]));
    }
    ((uint2*)h)[li] = *(uint2*)hv;
    ((uint2*)l)[li] = *(uint2*)lv;
}

// ---------------------------------------------------------------------------
// hgemm body: C = A·B^T + bias (bf16 hi/lo, 3-product), 128x128 tile,
// 512 threads, warp grid 4m x 4n (32x32 per warp), cp.async double-buffered.
// smem: buf{0,1} x {Ah,Al,Bh,Bl} tiles of 10240B (stride 80B) -> 81920B
// ---------------------------------------------------------------------------
static __device__ __forceinline__ void hgemm_body(
    const bf16* __restrict__ Ah, const bf16* __restrict__ Al,
    const bf16* __restrict__ Bh, const bf16* __restrict__ Bl,
    const float* __restrict__ bias, float* __restrict__ Cf,
    bf16* __restrict__ Ch, bf16* __restrict__ Cl,
    int K, int lda, int ldb, int ldc, char* sm)
{
    uint32_t sb = smem_u32(sm);
    int t = threadIdx.x, lane = t & 31, wid = t >> 5;
    int wm = wid & 3, wn = wid >> 2;          // 4 x 4 warps
    long m0 = blockIdx.y * 128, n0 = blockIdx.x * 128;

    const bf16* g0 = Ah + m0 * lda;
    const bf16* g1 = Al + m0 * lda;
    const bf16* g2 = Bh + n0 * ldb;
    const bf16* g3 = Bl + n0 * ldb;

#define G_ISSUE(c_, buf_) do {                                                  \
    int _c = (c_); uint32_t _bs = sb + (buf_) * 40960;                          \
    _Pragma("unroll")                                                           \
    for (int i = 0; i < 4; i++) {                                               \
        int w = t + 512 * i;                                                    \
        int tile = w >> 9, inner = w & 511;                                     \
        int row = inner >> 2, sg = inner & 3;                                   \
        const bf16* gp = (tile == 0 ? g0 : tile == 1 ? g1 : tile == 2 ? g2 : g3)\
            + (long)row * (tile < 2 ? lda : ldb) + _c * 32 + sg * 8;            \
        CP16(_bs + tile * 10240 + row * 80 + sg * 16, gp);                      \
    }                                                                           \
    CPCOMMIT();                                                                 \
} while (0)

    float acc[2][4][4] = {};
    int nc = K >> 5;
    G_ISSUE(0, 0);
    G_ISSUE(1, 1);
    for (int c = 0; c < nc; c++) {
        if (c + 1 < nc) { CPWAIT(1); } else { CPWAIT(0); }
        __syncthreads();
        uint32_t bAh = sb + (c & 1) * 40960, bAl = bAh + 10240;
        uint32_t bBh = bAh + 20480, bBl = bAh + 30720;
#pragma unroll
        for (int k0 = 0; k0 < 32; k0 += 16) {
            uint32_t ah[2][4], al[2][4], bhf[2][4], blf[2][4];
#pragma unroll
            for (int mt = 0; mt < 2; mt++) {
                ldsmA(ah[mt], bAh, wm * 32 + mt * 16, k0, 80, lane);
                ldsmA(al[mt], bAl, wm * 32 + mt * 16, k0, 80, lane);
            }
#pragma unroll
            for (int p = 0; p < 2; p++) {
                ldsmB(bhf[p], bBh, wn * 32 + p * 16, k0, 80, lane);
                ldsmB(blf[p], bBl, wn * 32 + p * 16, k0, 80, lane);
            }
#pragma unroll
            for (int mt = 0; mt < 2; mt++)
#pragma unroll
                for (int p = 0; p < 2; p++) {
                    mma3(acc[mt][p * 2],     ah[mt], al[mt], &bhf[p][0], &blf[p][0]);
                    mma3(acc[mt][p * 2 + 1], ah[mt], al[mt], &bhf[p][2], &blf[p][2]);
                }
        }
        __syncthreads();
        if (c + 2 < nc) G_ISSUE(c + 2, c & 1);
    }
#undef G_ISSUE

#pragma unroll
    for (int mt = 0; mt < 2; mt++)
#pragma unroll
        for (int nt = 0; nt < 4; nt++) {
            float* cc = acc[mt][nt];
            long r0 = m0 + wm * 32 + mt * 16 + (lane >> 2);
            int col = (int)n0 + wn * 32 + nt * 8 + 2 * (lane & 3);
            float b0 = bias[col], b1 = bias[col + 1];
            float f0 = cc[0] + b0, f1 = cc[1] + b1, f2 = cc[2] + b0, f3 = cc[3] + b1;
            if (Cf) {
                *(float2*)(Cf + r0 * ldc + col) = make_float2(f0, f1);
                *(float2*)(Cf + (r0 + 8) * ldc + col) = make_float2(f2, f3);
            }
            if (Ch) {
                store_split2(Ch, Cl, r0 * ldc + col, f0, f1);
                store_split2(Ch, Cl, (r0 + 8) * ldc + col, f2, f3);
            }
        }
}

// merged Q/K/V projections: blockIdx.z selects which GEMM
__global__ __launch_bounds__(512) void proj3(
    const bf16* __restrict__ qh, const bf16* __restrict__ ql,
    const bf16* __restrict__ xh, const bf16* __restrict__ xl,
    const bf16* __restrict__ wqh, const bf16* __restrict__ wql,
    const bf16* __restrict__ wkh, const bf16* __restrict__ wkl,
    const bf16* __restrict__ wvh, const bf16* __restrict__ wvl,
    const float* __restrict__ bq, const float* __restrict__ bk, const float* __restrict__ bv,
    bf16* __restrict__ Qh, bf16* __restrict__ Ql,
    bf16* __restrict__ Kh, bf16* __restrict__ Kl,
    bf16* __restrict__ Vh, bf16* __restrict__ Vl)
{
    extern __shared__ char sm[];
    int z = blockIdx.z;
    const bf16* Ah = (z == 0) ? qh : xh;
    const bf16* Al = (z == 0) ? ql : xl;
    const bf16* Bh = (z == 0) ? wqh : (z == 1) ? wkh : wvh;
    const bf16* Bl = (z == 0) ? wql : (z == 1) ? wkl : wvl;
    const float* bias = (z == 0) ? bq : (z == 1) ? bk : bv;
    bf16* Ch = (z == 0) ? Qh : (z == 1) ? Kh : Vh;
    bf16* Cl = (z == 0) ? Ql : (z == 1) ? Kl : Vl;
    hgemm_body(Ah, Al, Bh, Bl, bias, nullptr, Ch, Cl, 1024, 1024, 1024, 1024, sm);
}

// out projection (fp32 result)
__global__ __launch_bounds__(512) void hgemm_out(
    const bf16* __restrict__ Ah, const bf16* __restrict__ Al,
    const bf16* __restrict__ Bh, const bf16* __restrict__ Bl,
    const float* __restrict__ bias, float* __restrict__ Cf)
{
    extern __shared__ char sm[];
    hgemm_body(Ah, Al, Bh, Bl, bias, Cf, nullptr, nullptr, 1024, 1024, 1024, 1024, sm);
}

// ---------------------------------------------------------------------------
// vtrans: V split [4096 tok,1024] -> per (b,h): [64 d][2048 tok]
// ---------------------------------------------------------------------------
__global__ __launch_bounds__(256) void vtrans(
    const bf16* __restrict__ Vh, const bf16* __restrict__ Vl,
    bf16* __restrict__ Th, bf16* __restrict__ Tl) {
    __shared__ bf16 sh[64][72], sl[64][72];
    int t = threadIdx.x, tt = blockIdx.x, bh = blockIdx.y;
    int b = bh >> 4, h = bh & 15;
    const bf16* srch = Vh + ((long)b * 2048 + tt * 64) * 1024 + h * 64;
    const bf16* srcl = Vl + ((long)b * 2048 + tt * 64) * 1024 + h * 64;
#pragma unroll
    for (int i = 0; i < 2; i++) {
        int s = t + 256 * i, row = s >> 3, seg = s & 7;
        *(uint4*)&sh[row][seg * 8] = *(const uint4*)(srch + (long)row * 1024 + seg * 8);
        *(uint4*)&sl[row][seg * 8] = *(const uint4*)(srcl + (long)row * 1024 + seg * 8);
    }
    __syncthreads();
    bf16* dh = Th + (long)bh * 64 * 2048 + tt * 64;
    bf16* dl = Tl + (long)bh * 64 * 2048 + tt * 64;
#pragma unroll
    for (int i = 0; i < 2; i++) {
        int s = t + 256 * i, d = s >> 3, seg = s & 7;
        __align__(16) bf16 th[8], tl[8];
#pragma unroll
        for (int j = 0; j < 8; j++) { th[j] = sh[seg * 8 + j][d]; tl[j] = sl[seg * 8 + j][d]; }
        *(uint4*)(dh + (long)d * 2048 + seg * 8) = *(uint4*)th;
        *(uint4*)(dl + (long)d * 2048 + seg * 8) = *(uint4*)tl;
    }
}

// ---------------------------------------------------------------------------
// fused_attn, 512 threads, warp grid 4m x 4n.
// smem layout identical to r7 except part grows to 512 floats.
// ---------------------------------------------------------------------------
#define SQ_H  0
#define SQ_L  18432
#define SKBUF(b) (36864 + (b) * 36864)
#define SP_H  110592
#define SP_L  145408
#define SV_H  180224
#define SV_L  197632
#define SMSK  215040
#define SPART 223232
#define SINVS 225280
#define SM_FUSED 225792

__global__ __launch_bounds__(512, 1) void fused_attn(
    const bf16* __restrict__ Qh, const bf16* __restrict__ Ql,
    const bf16* __restrict__ Kh, const bf16* __restrict__ Kl,
    const bf16* __restrict__ Vth, const bf16* __restrict__ Vtl,
    const float* __restrict__ mask,
    float* __restrict__ A, bf16* __restrict__ Bh, bf16* __restrict__ Bl)
{
    extern __shared__ char sm[];
    uint32_t sb = smem_u32(sm);
    int t = threadIdx.x, lane = t & 31, wid = t >> 5;
    int wm = wid & 3, wn = wid >> 2;          // 4 x 4 warps
    int qt = blockIdx.x, bh = blockIdx.y;
    int b = bh >> 4, h = bh & 15;

    const bf16* qh = Qh + ((long)b * 2048 + qt * 128) * 1024 + h * 64;
    const bf16* ql = Ql + ((long)b * 2048 + qt * 128) * 1024 + h * 64;
    const bf16* kh = Kh + (long)b * 2048 * 1024 + h * 64;
    const bf16* kl = Kl + (long)b * 2048 * 1024 + h * 64;
    const bf16* vth = Vth + (long)bh * 64 * 2048;
    const bf16* vtl = Vtl + (long)bh * 64 * 2048;
    float* Abh = A + ((long)bh * 2048 + qt * 128) * 2048;
    const float* mrow = mask + (long)b * 2048;

    float* msk  = (float*)(sm + SMSK);
    float* part = (float*)(sm + SPART);
    float* invs = (float*)(sm + SINVS);

#define KISSUE(kt_, buf_) do {                                                   \
    int _kt = (kt_); uint32_t _kb = sb + SKBUF(buf_);                            \
    _Pragma("unroll")                                                            \
    for (int i = 0; i < 4; i++) {                                                \
        int w = t + 512 * i;                                                     \
        int tile = w >> 10, inner = w & 1023;                                    \
        int row = inner >> 3, sg = inner & 7;                                    \
        const bf16* src = (tile ? kl : kh) + (long)(_kt * 128 + row) * 1024 + sg * 8; \
        CP16(_kb + tile * 18432 + row * 144 + sg * 16, src);                     \
    }                                                                            \
    CPCOMMIT();                                                                  \
} while (0)

#define VISSUE(kt_) do {                                                         \
    int _kt = (kt_);                                                             \
    _Pragma("unroll")                                                            \
    for (int i = 0; i < 4; i++) {                                                \
        int w = t + 512 * i;                                                     \
        int tile = w >> 10, inner = w & 1023;                                    \
        int row = inner >> 4, sg = inner & 15;                                   \
        const bf16* src = (tile ? vtl : vth) + (long)row * 2048 + _kt * 128 + sg * 8; \
        CP16(sb + (tile ? SV_L : SV_H) + row * 272 + sg * 16, src);              \
    }                                                                            \
    CPCOMMIT();                                                                  \
} while (0)

    // prologue
    KISSUE(0, 0);
#pragma unroll
    for (int i = 0; i < 4; i++) {
        int w = t + 512 * i;
        int tile = w >> 10, inner = w & 1023;
        int row = inner >> 3, sg = inner & 7;
        const bf16* src = (tile ? ql : qh) + (long)row * 1024 + sg * 8;
        *(uint4*)(sm + (tile ? SQ_L : SQ_H) + row * 144 + sg * 16) = *(const uint4*)src;
    }
#pragma unroll
    for (int j = 0; j < 4; j++) {
        int idx = t + 512 * j;
        msk[idx] = (1.0f - mrow[idx]) * (-1e9f);
    }

    // ---------------- pass A: rowsum only ----------------
    float rs[4] = {0.f, 0.f, 0.f, 0.f};
    for (int kt = 0; kt < 16; kt++) {
        CPWAIT(0);
        __syncthreads();
        if (kt + 1 < 16) KISSUE(kt + 1, (kt + 1) & 1);

        uint32_t kb = sb + SKBUF(kt & 1);
        float acc[2][4][4] = {};
#pragma unroll
        for (int k0 = 0; k0 < 64; k0 += 16) {
            uint32_t ah[2][4], al[2][4], bhf[2][4], blf[2][4];
#pragma unroll
            for (int mt = 0; mt < 2; mt++) {
                ldsmA(ah[mt], sb + SQ_H, wm * 32 + mt * 16, k0, 144, lane);
                ldsmA(al[mt], sb + SQ_L, wm * 32 + mt * 16, k0, 144, lane);
            }
#pragma unroll
            for (int p = 0; p < 2; p++) {
                ldsmB(bhf[p], kb,         wn * 32 + p * 16, k0, 144, lane);
                ldsmB(blf[p], kb + 18432, wn * 32 + p * 16, k0, 144, lane);
            }
#pragma unroll
            for (int mt = 0; mt < 2; mt++)
#pragma unroll
                for (int p = 0; p < 2; p++) {
                    mma3(acc[mt][p * 2],     ah[mt], al[mt], &bhf[p][0], &blf[p][0]);
                    mma3(acc[mt][p * 2 + 1], ah[mt], al[mt], &bhf[p][2], &blf[p][2]);
                }
        }
#pragma unroll
        for (int mt = 0; mt < 2; mt++)
#pragma unroll
            for (int nt = 0; nt < 4; nt++) {
                float* cc = acc[mt][nt];
                int cl = kt * 128 + wn * 32 + nt * 8 + 2 * (lane & 3);
                float m0v = msk[cl], m1v = msk[cl + 1];
                rs[mt * 2 + 0] += __expf(cc[0] + m0v) + __expf(cc[1] + m1v);
                rs[mt * 2 + 1] += __expf(cc[2] + m0v) + __expf(cc[3] + m1v);
            }
    }

    KISSUE(0, 0);     // K(0) for pass B

    // reduce rowsum -> invs[128]
#pragma unroll
    for (int i = 0; i < 4; i++) {
        rs[i] += __shfl_xor_sync(0xffffffffu, rs[i], 1);
        rs[i] += __shfl_xor_sync(0xffffffffu, rs[i], 2);
    }
    __syncthreads();
    if ((lane & 3) == 0) {
#pragma unroll
        for (int mt = 0; mt < 2; mt++)
#pragma unroll
            for (int hf = 0; hf < 2; hf++)
                part[wn * 128 + wm * 32 + mt * 16 + hf * 8 + (lane >> 2)] = rs[mt * 2 + hf];
    }
    __syncthreads();
    if (t < 128)
        invs[t] = 1.0f / (part[t] + part[128 + t] + part[256 + t] + part[384 + t]);
    __syncthreads();

    float invr[2][2];
#pragma unroll
    for (int mt = 0; mt < 2; mt++) {
        invr[mt][0] = invs[wm * 32 + mt * 16 + (lane >> 2)];
        invr[mt][1] = invs[wm * 32 + mt * 16 + 8 + (lane >> 2)];
    }

    // ---------------- pass B ----------------
    float oacc[2][2][4] = {};
    for (int kt = 0; kt < 16; kt++) {
        CPWAIT(0);
        __syncthreads();
        VISSUE(kt);
        if (kt + 1 < 16) KISSUE(kt + 1, (kt + 1) & 1);

        uint32_t kb = sb + SKBUF(kt & 1);
        float acc[2][4][4] = {};
#pragma unroll
        for (int k0 = 0; k0 < 64; k0 += 16) {
            uint32_t ah[2][4], al[2][4], bhf[2][4], blf[2][4];
#pragma unroll
            for (int mt = 0; mt < 2; mt++) {
                ldsmA(ah[mt], sb + SQ_H, wm * 32 + mt * 16, k0, 144, lane);
                ldsmA(al[mt], sb + SQ_L, wm * 32 + mt * 16, k0, 144, lane);
            }
#pragma unroll
            for (int p = 0; p < 2; p++) {
                ldsmB(bhf[p], kb,         wn * 32 + p * 16, k0, 144, lane);
                ldsmB(blf[p], kb + 18432, wn * 32 + p * 16, k0, 144, lane);
            }
#pragma unroll
            for (int mt = 0; mt < 2; mt++)
#pragma unroll
                for (int p = 0; p < 2; p++) {
                    mma3(acc[mt][p * 2],     ah[mt], al[mt], &bhf[p][0], &blf[p][0]);
                    mma3(acc[mt][p * 2 + 1], ah[mt], al[mt], &bhf[p][2], &blf[p][2]);
                }
        }

        // epilogue: normalize, write attn, split P -> smem
#pragma unroll
        for (int mt = 0; mt < 2; mt++)
#pragma unroll
            for (int nt = 0; nt < 4; nt++) {
                float* cc = acc[mt][nt];
                int r0 = wm * 32 + mt * 16 + (lane >> 2);
                int cl = wn * 32 + nt * 8 + 2 * (lane & 3);
                float m0v = msk[kt * 128 + cl], m1v = msk[kt * 128 + cl + 1];
                float e0 = __expf(cc[0] + m0v) * invr[mt][0];
                float e1 = __expf(cc[1] + m1v) * invr[mt][0];
                float e2 = __expf(cc[2] + m0v) * invr[mt][1];
                float e3 = __expf(cc[3] + m1v) * invr[mt][1];
                *(float2*)(Abh + (long)r0 * 2048 + kt * 128 + cl)       = make_float2(e0, e1);
                *(float2*)(Abh + (long)(r0 + 8) * 2048 + kt * 128 + cl) = make_float2(e2, e3);
                smem_split2(sm + SP_H + r0 * 272 + cl * 2,
                            sm + SP_L + r0 * 272 + cl * 2, e0, e1);
                smem_split2(sm + SP_H + (r0 + 8) * 272 + cl * 2,
                            sm + SP_L + (r0 + 8) * 272 + cl * 2, e2, e3);
            }

        if (kt + 1 < 16) { CPWAIT(1); } else { CPWAIT(0); }
        __syncthreads();

        // O += P · V^T  (warp covers rows wm*32, cols wn*16)
#pragma unroll
        for (int k0 = 0; k0 < 128; k0 += 16) {
            uint32_t ah[2][4], al[2][4], bhf[4], blf[4];
#pragma unroll
            for (int mt = 0; mt < 2; mt++) {
                ldsmA(ah[mt], sb + SP_H, wm * 32 + mt * 16, k0, 272, lane);
                ldsmA(al[mt], sb + SP_L, wm * 32 + mt * 16, k0, 272, lane);
            }
            ldsmB(bhf, sb + SV_H, wn * 16, k0, 272, lane);
            ldsmB(blf, sb + SV_L, wn * 16, k0, 272, lane);
#pragma unroll
            for (int mt = 0; mt < 2; mt++) {
                mma3(oacc[mt][0], ah[mt], al[mt], &bhf[0], &blf[0]);
                mma3(oacc[mt][1], ah[mt], al[mt], &bhf[2], &blf[2]);
            }
        }
    }

    // write blended split [b, q, h*64+d]
#pragma unroll
    for (int mt = 0; mt < 2; mt++)
#pragma unroll
        for (int nt = 0; nt < 2; nt++) {
            float* cc = oacc[mt][nt];
            long r0 = (long)b * 2048 + qt * 128 + wm * 32 + mt * 16 + (lane >> 2);
            int col = h * 64 + wn * 16 + nt * 8 + 2 * (lane & 3);
            store_split2(Bh, Bl, r0 * 1024 + col, cc[0], cc[1]);
            store_split2(Bh, Bl, (r0 + 8) * 1024 + col, cc[2], cc[3]);
        }
}

// ===========================================================================
extern "C" void kernel_launch(void* const* d_in, const int* in_sizes, int n_in,
                              void* d_out, int out_size) {
    (void)in_sizes; (void)n_in;
    const float* query        = (const float*)d_in[0];
    const float* input_embeds = (const float*)d_in[1];
    const float* mask         = (const float*)d_in[2];
    const float* wq_w = (const float*)d_in[3];
    const float* wq_b = (const float*)d_in[4];
    const float* wk_w = (const float*)d_in[5];
    const float* wk_b = (const float*)d_in[6];
    const float* wv_w = (const float*)d_in[7];
    const float* wv_b = (const float*)d_in[8];
    const float* wo_w = (const float*)d_in[9];
    const float* wo_b = (const float*)d_in[10];
    float* out = (float*)d_out;

    bf16 *qh, *ql, *xh, *xl, *wqh, *wql, *wkh, *wkl, *wvh, *wvl, *woh, *wol;
    bf16 *Qh, *Ql, *Kh, *Kl, *Vh, *Vl, *Vth, *Vtl, *Bh, *Bl;
    float *attn_scratch;
    cudaGetSymbolAddress((void**)&qh, g_qh);   cudaGetSymbolAddress((void**)&ql, g_ql);
    cudaGetSymbolAddress((void**)&xh, g_xh);   cudaGetSymbolAddress((void**)&xl, g_xl);
    cudaGetSymbolAddress((void**)&wqh, g_wqh); cudaGetSymbolAddress((void**)&wql, g_wql);
    cudaGetSymbolAddress((void**)&wkh, g_wkh); cudaGetSymbolAddress((void**)&wkl, g_wkl);
    cudaGetSymbolAddress((void**)&wvh, g_wvh); cudaGetSymbolAddress((void**)&wvl, g_wvl);
    cudaGetSymbolAddress((void**)&woh, g_woh); cudaGetSymbolAddress((void**)&wol, g_wol);
    cudaGetSymbolAddress((void**)&Qh, g_Qh);   cudaGetSymbolAddress((void**)&Ql, g_Ql);
    cudaGetSymbolAddress((void**)&Kh, g_Kh);   cudaGetSymbolAddress((void**)&Kl, g_Kl);
    cudaGetSymbolAddress((void**)&Vh, g_Vh);   cudaGetSymbolAddress((void**)&Vl, g_Vl);
    cudaGetSymbolAddress((void**)&Vth, g_Vth); cudaGetSymbolAddress((void**)&Vtl, g_Vtl);
    cudaGetSymbolAddress((void**)&Bh, g_Bh);   cudaGetSymbolAddress((void**)&Bl, g_Bl);
    cudaGetSymbolAddress((void**)&attn_scratch, g_attn);

    const long OUT_E = 4194304L, ATTN_E = 134217728L;
    float* attn = ((long)out_size >= OUT_E + ATTN_E) ? (out + OUT_E) : attn_scratch;

    const int SM_GEMM = 81920;
    cudaFuncSetAttribute(proj3,      cudaFuncAttributeMaxDynamicSharedMemorySize, SM_GEMM);
    cudaFuncSetAttribute(hgemm_out,  cudaFuncAttributeMaxDynamicSharedMemorySize, SM_GEMM);
    cudaFuncSetAttribute(fused_attn, cudaFuncAttributeMaxDynamicSharedMemorySize, SM_FUSED);

    cvt_all<<<12288, 256>>>(query, input_embeds, wq_w, wk_w, wv_w, wo_w,
                            qh, ql, xh, xl, wqh, wql, wkh, wkl, wvh, wvl, woh, wol);

    proj3<<<dim3(8, 32, 3), 512, SM_GEMM>>>(qh, ql, xh, xl,
                                            wqh, wql, wkh, wkl, wvh, wvl,
                                            wq_b, wk_b, wv_b,
                                            Qh, Ql, Kh, Kl, Vh, Vl);

    vtrans<<<dim3(32, 32), 256>>>(Vh, Vl, Vth, Vtl);

    fused_attn<<<dim3(16, 32), 512, SM_FUSED>>>(Qh, Ql, Kh, Kl, Vth, Vtl, mask,
                                                attn, Bh, Bl);

    hgemm_out<<<dim3(8, 32), 512, SM_GEMM>>>(Bh, Bl, woh, wol, wo_b, out);
}

// round 9
// speedup vs baseline: 1.0871x; 1.0871x over previous
#include <cuda_runtime.h>
#include <cuda_bf16.h>
#include <cstdint>

typedef __nv_bfloat16 bf16;

// ---------------------------------------------------------------------------
static __device__ __forceinline__ uint32_t smem_u32(const void* p) {
    uint32_t a;
    asm("{ .reg .u64 t; cvta.to.shared.u64 t, %1; cvt.u32.u64 %0, t; }" : "=r"(a) : "l"(p));
    return a;
}
static __device__ __forceinline__ void mma16816(float* c, const uint32_t* a, const uint32_t* b) {
    asm volatile("mma.sync.aligned.m16n8k16.row.col.f32.bf16.bf16.f32 "
        "{%0,%1,%2,%3}, {%4,%5,%6,%7}, {%8,%9}, {%0,%1,%2,%3};"
        : "+f"(c[0]), "+f"(c[1]), "+f"(c[2]), "+f"(c[3])
        : "r"(a[0]), "r"(a[1]), "r"(a[2]), "r"(a[3]), "r"(b[0]), "r"(b[1]));
}
static __device__ __forceinline__ void mma3(float* c, const uint32_t* ah, const uint32_t* al,
                                            const uint32_t* bh, const uint32_t* bl) {
    mma16816(c, ah, bh); mma16816(c, ah, bl); mma16816(c, al, bh);
}
static __device__ __forceinline__ void ldsm4(uint32_t* r, uint32_t a) {
    asm volatile("ldmatrix.sync.aligned.m8n8.x4.shared.b16 {%0,%1,%2,%3}, [%4];"
        : "=r"(r[0]), "=r"(r[1]), "=r"(r[2]), "=r"(r[3]) : "r"(a));
}
static __device__ __forceinline__ void ldsmA(uint32_t* r, uint32_t base, int m0, int k0, int sbytes, int lane) {
    ldsm4(r, base + (uint32_t)((m0 + (lane & 7) + ((lane >> 3) & 1) * 8) * sbytes
                               + (k0 + ((lane >> 4) << 3)) * 2));
}
static __device__ __forceinline__ void ldsmB(uint32_t* r, uint32_t base, int n0, int k0, int sbytes, int lane) {
    ldsm4(r, base + (uint32_t)((n0 + (lane & 7) + ((lane >> 4) << 3)) * sbytes
                               + (k0 + (((lane >> 3) & 1) << 3)) * 2));
}
#define CP16(sm_, gp_) asm volatile("cp.async.cg.shared.global [%0], [%1], 16;" :: "r"(sm_), "l"(gp_))
#define CPCOMMIT()     asm volatile("cp.async.commit_group;")
#define CPWAIT(n)      asm volatile("cp.async.wait_group %0;" :: "n"(n))

static __device__ __forceinline__ void store_split2(bf16* Ch, bf16* Cl, long off, float x, float y) {
    __align__(4) bf16 h[2] = {__float2bfloat16(x), __float2bfloat16(y)};
    __align__(4) bf16 l[2] = {__float2bfloat16(x - __bfloat162float(h[0])),
                              __float2bfloat16(y - __bfloat162float(h[1]))};
    *(uint32_t*)(Ch + off) = *(uint32_t*)h;
    *(uint32_t*)(Cl + off) = *(uint32_t*)l;
}
static __device__ __forceinline__ void smem_split2(char* ph, char* pl, float x, float y) {
    __align__(4) bf16 h[2] = {__float2bfloat16(x), __float2bfloat16(y)};
    __align__(4) bf16 l[2] = {__float2bfloat16(x - __bfloat162float(h[0])),
                              __float2bfloat16(y - __bfloat162float(h[1]))};
    *(uint32_t*)ph = *(uint32_t*)h;
    *(uint32_t*)pl = *(uint32_t*)l;
}

// ---------------- scratch ----------------
__device__ bf16 g_qh[4194304], g_ql[4194304];
__device__ bf16 g_xh[4194304], g_xl[4194304];
__device__ bf16 g_wqh[1048576], g_wql[1048576];
__device__ bf16 g_wkh[1048576], g_wkl[1048576];
__device__ bf16 g_wvh[1048576], g_wvl[1048576];
__device__ bf16 g_woh[1048576], g_wol[1048576];
__device__ bf16 g_Qh[4194304], g_Ql[4194304];
__device__ bf16 g_Kh[4194304], g_Kl[4194304];
__device__ bf16 g_Vh[4194304], g_Vl[4194304];
__device__ bf16 g_Vth[4194304], g_Vtl[4194304];  // [bh][64 d][2048 tok]
__device__ bf16 g_Bh[4194304], g_Bl[4194304];
__device__ float g_attn[134217728];

// ---------------- merged fp32 -> bf16 hi/lo for all 6 tensors ----------------
__global__ __launch_bounds__(256) void cvt_all(
    const float* __restrict__ s0, const float* __restrict__ s1,
    const float* __restrict__ s2, const float* __restrict__ s3,
    const float* __restrict__ s4, const float* __restrict__ s5,
    bf16* __restrict__ h0, bf16* __restrict__ l0, bf16* __restrict__ h1, bf16* __restrict__ l1,
    bf16* __restrict__ h2, bf16* __restrict__ l2, bf16* __restrict__ h3, bf16* __restrict__ l3,
    bf16* __restrict__ h4, bf16* __restrict__ l4, bf16* __restrict__ h5, bf16* __restrict__ l5)
{
    long i = (long)blockIdx.x * 256 + threadIdx.x;   // < 3145728
    const float* src; bf16 *h, *l; long li;
    if (i < 1048576)      { src = s0; h = h0; l = l0; li = i; }
    else if (i < 2097152) { src = s1; h = h1; l = l1; li = i - 1048576; }
    else {
        long j = i - 2097152;
        int w = (int)(j >> 18);
        li = j & 262143;
        src = (w == 0) ? s2 : (w == 1) ? s3 : (w == 2) ? s4 : s5;
        h   = (w == 0) ? h2 : (w == 1) ? h3 : (w == 2) ? h4 : h5;
        l   = (w == 0) ? l2 : (w == 1) ? l3 : (w == 2) ? l4 : l5;
    }
    float4 v = ((const float4*)src)[li];
    float f[4] = {v.x, v.y, v.z, v.w};
    __align__(8) bf16 hv[4], lv[4];
#pragma unroll
    for (int j = 0; j < 4; j++) {
        hv[j] = __float2bfloat16(f[j]);
        lv[j] = __float2bfloat16(f[j] - __bfloat162float(hv[j]));
    }
    ((uint2*)h)[li] = *(uint2*)hv;
    ((uint2*)l)[li] = *(uint2*)lv;
}

// ---------------------------------------------------------------------------
// hgemm body (round-7 proven config): 256 threads, warp grid 4m x 2n,
// 128x128 tile, BK=32, cp.async double-buffered, smem 81920B -> 2 CTAs/SM.
// ---------------------------------------------------------------------------
static __device__ __forceinline__ void hgemm_body(
    const bf16* __restrict__ Ah, const bf16* __restrict__ Al,
    const bf16* __restrict__ Bh, const bf16* __restrict__ Bl,
    const float* __restrict__ bias, float* __restrict__ Cf,
    bf16* __restrict__ Ch, bf16* __restrict__ Cl,
    int K, int lda, int ldb, int ldc, char* sm)
{
    uint32_t sb = smem_u32(sm);
    int t = threadIdx.x, lane = t & 31, wid = t >> 5;
    int wm = wid & 3, wn = wid >> 2;          // 4m x 2n, warp tile 32x64
    long m0 = blockIdx.y * 128, n0 = blockIdx.x * 128;

    const bf16* g0 = Ah + m0 * lda;
    const bf16* g1 = Al + m0 * lda;
    const bf16* g2 = Bh + n0 * ldb;
    const bf16* g3 = Bl + n0 * ldb;

#define G_ISSUE(c_, buf_) do {                                                  \
    int _c = (c_); uint32_t _bs = sb + (buf_) * 40960;                          \
    _Pragma("unroll")                                                           \
    for (int i = 0; i < 8; i++) {                                               \
        const int tile = i >> 1;                                                \
        int w = t + 256 * (i & 1);                                              \
        int row = w >> 2, sg = w & 3;                                           \
        const bf16* gp = (tile == 0 ? g0 : tile == 1 ? g1 : tile == 2 ? g2 : g3)\
            + (long)row * (tile < 2 ? lda : ldb) + _c * 32 + sg * 8;            \
        CP16(_bs + tile * 10240 + row * 80 + sg * 16, gp);                      \
    }                                                                           \
    CPCOMMIT();                                                                 \
} while (0)

    float acc[2][8][4] = {};
    int nc = K >> 5;
    G_ISSUE(0, 0);
    G_ISSUE(1, 1);
    for (int c = 0; c < nc; c++) {
        if (c + 1 < nc) { CPWAIT(1); } else { CPWAIT(0); }
        __syncthreads();
        uint32_t bAh = sb + (c & 1) * 40960, bAl = bAh + 10240;
        uint32_t bBh = bAh + 20480, bBl = bAh + 30720;
#pragma unroll
        for (int k0 = 0; k0 < 32; k0 += 16) {
            uint32_t ah[2][4], al[2][4], bhf[4][4], blf[4][4];
#pragma unroll
            for (int mt = 0; mt < 2; mt++) {
                ldsmA(ah[mt], bAh, wm * 32 + mt * 16, k0, 80, lane);
                ldsmA(al[mt], bAl, wm * 32 + mt * 16, k0, 80, lane);
            }
#pragma unroll
            for (int p = 0; p < 4; p++) {
                ldsmB(bhf[p], bBh, wn * 64 + p * 16, k0, 80, lane);
                ldsmB(blf[p], bBl, wn * 64 + p * 16, k0, 80, lane);
            }
#pragma unroll
            for (int mt = 0; mt < 2; mt++)
#pragma unroll
                for (int p = 0; p < 4; p++) {
                    mma3(acc[mt][p * 2],     ah[mt], al[mt], &bhf[p][0], &blf[p][0]);
                    mma3(acc[mt][p * 2 + 1], ah[mt], al[mt], &bhf[p][2], &blf[p][2]);
                }
        }
        __syncthreads();
        if (c + 2 < nc) G_ISSUE(c + 2, c & 1);
    }
#undef G_ISSUE

#pragma unroll
    for (int mt = 0; mt < 2; mt++)
#pragma unroll
        for (int nt = 0; nt < 8; nt++) {
            float* cc = acc[mt][nt];
            long r0 = m0 + wm * 32 + mt * 16 + (lane >> 2);
            int col = (int)n0 + wn * 64 + nt * 8 + 2 * (lane & 3);
            float b0 = bias[col], b1 = bias[col + 1];
            float f0 = cc[0] + b0, f1 = cc[1] + b1, f2 = cc[2] + b0, f3 = cc[3] + b1;
            if (Cf) {
                *(float2*)(Cf + r0 * ldc + col) = make_float2(f0, f1);
                *(float2*)(Cf + (r0 + 8) * ldc + col) = make_float2(f2, f3);
            }
            if (Ch) {
                store_split2(Ch, Cl, r0 * ldc + col, f0, f1);
                store_split2(Ch, Cl, (r0 + 8) * ldc + col, f2, f3);
            }
        }
}

// merged Q/K/V projections: blockIdx.z selects which GEMM
__global__ __launch_bounds__(256) void proj3(
    const bf16* __restrict__ qh, const bf16* __restrict__ ql,
    const bf16* __restrict__ xh, const bf16* __restrict__ xl,
    const bf16* __restrict__ wqh, const bf16* __restrict__ wql,
    const bf16* __restrict__ wkh, const bf16* __restrict__ wkl,
    const bf16* __restrict__ wvh, const bf16* __restrict__ wvl,
    const float* __restrict__ bq, const float* __restrict__ bk, const float* __restrict__ bv,
    bf16* __restrict__ Qh, bf16* __restrict__ Ql,
    bf16* __restrict__ Kh, bf16* __restrict__ Kl,
    bf16* __restrict__ Vh, bf16* __restrict__ Vl)
{
    extern __shared__ char sm[];
    int z = blockIdx.z;
    const bf16* Ah = (z == 0) ? qh : xh;
    const bf16* Al = (z == 0) ? ql : xl;
    const bf16* Bh = (z == 0) ? wqh : (z == 1) ? wkh : wvh;
    const bf16* Bl = (z == 0) ? wql : (z == 1) ? wkl : wvl;
    const float* bias = (z == 0) ? bq : (z == 1) ? bk : bv;
    bf16* Ch = (z == 0) ? Qh : (z == 1) ? Kh : Vh;
    bf16* Cl = (z == 0) ? Ql : (z == 1) ? Kl : Vl;
    hgemm_body(Ah, Al, Bh, Bl, bias, nullptr, Ch, Cl, 1024, 1024, 1024, 1024, sm);
}

__global__ __launch_bounds__(256) void hgemm_out(
    const bf16* __restrict__ Ah, const bf16* __restrict__ Al,
    const bf16* __restrict__ Bh, const bf16* __restrict__ Bl,
    const float* __restrict__ bias, float* __restrict__ Cf)
{
    extern __shared__ char sm[];
    hgemm_body(Ah, Al, Bh, Bl, bias, Cf, nullptr, nullptr, 1024, 1024, 1024, 1024, sm);
}

// ---------------------------------------------------------------------------
// vtrans: V split [4096 tok,1024] -> per (b,h): [64 d][2048 tok]
// ---------------------------------------------------------------------------
__global__ __launch_bounds__(256) void vtrans(
    const bf16* __restrict__ Vh, const bf16* __restrict__ Vl,
    bf16* __restrict__ Th, bf16* __restrict__ Tl) {
    __shared__ bf16 sh[64][72], sl[64][72];
    int t = threadIdx.x, tt = blockIdx.x, bh = blockIdx.y;
    int b = bh >> 4, h = bh & 15;
    const bf16* srch = Vh + ((long)b * 2048 + tt * 64) * 1024 + h * 64;
    const bf16* srcl = Vl + ((long)b * 2048 + tt * 64) * 1024 + h * 64;
#pragma unroll
    for (int i = 0; i < 2; i++) {
        int s = t + 256 * i, row = s >> 3, seg = s & 7;
        *(uint4*)&sh[row][seg * 8] = *(const uint4*)(srch + (long)row * 1024 + seg * 8);
        *(uint4*)&sl[row][seg * 8] = *(const uint4*)(srcl + (long)row * 1024 + seg * 8);
    }
    __syncthreads();
    bf16* dh = Th + (long)bh * 64 * 2048 + tt * 64;
    bf16* dl = Tl + (long)bh * 64 * 2048 + tt * 64;
#pragma unroll
    for (int i = 0; i < 2; i++) {
        int s = t + 256 * i, d = s >> 3, seg = s & 7;
        __align__(16) bf16 th[8], tl[8];
#pragma unroll
        for (int j = 0; j < 8; j++) { th[j] = sh[seg * 8 + j][d]; tl[j] = sl[seg * 8 + j][d]; }
        *(uint4*)(dh + (long)d * 2048 + seg * 8) = *(uint4*)th;
        *(uint4*)(dl + (long)d * 2048 + seg * 8) = *(uint4*)tl;
    }
}

// ---------------------------------------------------------------------------
// fused_attn: 256 threads, 64-q tile, 64-wide K tiles, 2 CTAs/SM.
// pass A: rowsum of exp(QK^T + maskadd); pass B: recompute, write attn, O+=P·V
// smem (bytes), all tiles stride 144:
//   Q hi @0, Q lo @9216
//   K buf0 @18432 (hi,lo 9216 each), buf1 @36864
//   P hi @55296, P lo @64512
//   V hi @73728, V lo @82944
//   part @92160 (4x64 f), invs @93184 (64 f) -> total 93440; x2 CTAs = 187KB
// ---------------------------------------------------------------------------
#define FQ_H  0
#define FQ_L  9216
#define FKBUF(b) (18432 + (b) * 18432)
#define FP_H  55296
#define FP_L  64512
#define FV_H  73728
#define FV_L  82944
#define FPART 92160
#define FINVS 93184
#define SM_FUSED 93440

__global__ __launch_bounds__(256, 2) void fused_attn(
    const bf16* __restrict__ Qh, const bf16* __restrict__ Ql,
    const bf16* __restrict__ Kh, const bf16* __restrict__ Kl,
    const bf16* __restrict__ Vth, const bf16* __restrict__ Vtl,
    const float* __restrict__ mask,
    float* __restrict__ A, bf16* __restrict__ Bh, bf16* __restrict__ Bl)
{
    extern __shared__ char sm[];
    uint32_t sb = smem_u32(sm);
    int t = threadIdx.x, lane = t & 31, wid = t >> 5;
    int wm = wid & 1, wn = wid >> 1;          // 2m x 4n; warp tile 32q x 16k
    int qt = blockIdx.x, bh = blockIdx.y;     // qt: 64-row stripe
    int b = bh >> 4, h = bh & 15;

    const bf16* qh = Qh + ((long)b * 2048 + qt * 64) * 1024 + h * 64;
    const bf16* ql = Ql + ((long)b * 2048 + qt * 64) * 1024 + h * 64;
    const bf16* kh = Kh + (long)b * 2048 * 1024 + h * 64;
    const bf16* kl = Kl + (long)b * 2048 * 1024 + h * 64;
    const bf16* vth = Vth + (long)bh * 64 * 2048;
    const bf16* vtl = Vtl + (long)bh * 64 * 2048;
    float* Abh = A + ((long)bh * 2048 + qt * 64) * 2048;
    const float* mrow = mask + (long)b * 2048;

    float* part = (float*)(sm + FPART);
    float* invs = (float*)(sm + FINVS);

// K tile kt (64 k-rows x 64 d, hi+lo) -> buffer buf. 1024 segs, 4/thread.
#define KISSUE(kt_, buf_) do {                                                   \
    int _kt = (kt_); uint32_t _kb = sb + FKBUF(buf_);                            \
    _Pragma("unroll")                                                            \
    for (int i = 0; i < 4; i++) {                                                \
        int w = t + 256 * i;                                                     \
        int tile = w >> 9, inner = w & 511;                                      \
        int row = inner >> 3, sg = inner & 7;                                    \
        const bf16* src = (tile ? kl : kh) + (long)(_kt * 64 + row) * 1024 + sg * 8; \
        CP16(_kb + tile * 9216 + row * 144 + sg * 16, src);                      \
    }                                                                            \
    CPCOMMIT();                                                                  \
} while (0)

// V tile kt (64 d-rows x 64 k, hi+lo)
#define VISSUE(kt_) do {                                                         \
    int _kt = (kt_);                                                             \
    _Pragma("unroll")                                                            \
    for (int i = 0; i < 4; i++) {                                                \
        int w = t + 256 * i;                                                     \
        int tile = w >> 9, inner = w & 511;                                      \
        int row = inner >> 3, sg = inner & 7;                                    \
        const bf16* src = (tile ? vtl : vth) + (long)row * 2048 + _kt * 64 + sg * 8; \
        CP16(sb + (tile ? FV_L : FV_H) + row * 144 + sg * 16, src);              \
    }                                                                            \
    CPCOMMIT();                                                                  \
} while (0)

    // prologue: K(0) async, Q tiles plain
    KISSUE(0, 0);
#pragma unroll
    for (int i = 0; i < 4; i++) {
        int w = t + 256 * i;
        int tile = w >> 9, inner = w & 511;
        int row = inner >> 3, sg = inner & 7;
        const bf16* src = (tile ? ql : qh) + (long)row * 1024 + sg * 8;
        *(uint4*)(sm + (tile ? FQ_L : FQ_H) + row * 144 + sg * 16) = *(const uint4*)src;
    }

    // ---------------- pass A: rowsum only ----------------
    float rs[4] = {0.f, 0.f, 0.f, 0.f};
    for (int kt = 0; kt < 32; kt++) {
        CPWAIT(0);
        __syncthreads();
        if (kt + 1 < 32) KISSUE(kt + 1, (kt + 1) & 1);

        uint32_t kb = sb + FKBUF(kt & 1);
        float acc[2][2][4] = {};
#pragma unroll
        for (int k0 = 0; k0 < 64; k0 += 16) {
            uint32_t ah[2][4], al[2][4], bhf[4], blf[4];
#pragma unroll
            for (int mt = 0; mt < 2; mt++) {
                ldsmA(ah[mt], sb + FQ_H, wm * 32 + mt * 16, k0, 144, lane);
                ldsmA(al[mt], sb + FQ_L, wm * 32 + mt * 16, k0, 144, lane);
            }
            ldsmB(bhf, kb,        wn * 16, k0, 144, lane);
            ldsmB(blf, kb + 9216, wn * 16, k0, 144, lane);
#pragma unroll
            for (int mt = 0; mt < 2; mt++) {
                mma3(acc[mt][0], ah[mt], al[mt], &bhf[0], &blf[0]);
                mma3(acc[mt][1], ah[mt], al[mt], &bhf[2], &blf[2]);
            }
        }
#pragma unroll
        for (int nt = 0; nt < 2; nt++) {
            int cl = kt * 64 + wn * 16 + nt * 8 + 2 * (lane & 3);
            float m0v = (1.0f - mrow[cl]) * (-1e9f);
            float m1v = (1.0f - mrow[cl + 1]) * (-1e9f);
#pragma unroll
            for (int mt = 0; mt < 2; mt++) {
                float* cc = acc[mt][nt];
                rs[mt * 2 + 0] += __expf(cc[0] + m0v) + __expf(cc[1] + m1v);
                rs[mt * 2 + 1] += __expf(cc[2] + m0v) + __expf(cc[3] + m1v);
            }
        }
    }

    KISSUE(0, 0);     // K(0) for pass B

    // reduce rowsum -> invs[64]
#pragma unroll
    for (int i = 0; i < 4; i++) {
        rs[i] += __shfl_xor_sync(0xffffffffu, rs[i], 1);
        rs[i] += __shfl_xor_sync(0xffffffffu, rs[i], 2);
    }
    __syncthreads();
    if ((lane & 3) == 0) {
#pragma unroll
        for (int mt = 0; mt < 2; mt++)
#pragma unroll
            for (int hf = 0; hf < 2; hf++)
                part[wn * 64 + wm * 32 + mt * 16 + hf * 8 + (lane >> 2)] = rs[mt * 2 + hf];
    }
    __syncthreads();
    if (t < 64)
        invs[t] = 1.0f / (part[t] + part[64 + t] + part[128 + t] + part[192 + t]);
    __syncthreads();

    float invr[2][2];
#pragma unroll
    for (int mt = 0; mt < 2; mt++) {
        invr[mt][0] = invs[wm * 32 + mt * 16 + (lane >> 2)];
        invr[mt][1] = invs[wm * 32 + mt * 16 + 8 + (lane >> 2)];
    }

    // ---------------- pass B ----------------
    float oacc[2][2][4] = {};
    for (int kt = 0; kt < 32; kt++) {
        CPWAIT(0);
        __syncthreads();                   // K(kt) ready; prior P/V reads done
        VISSUE(kt);                        // V first (released by wait_group 1)
        if (kt + 1 < 32) KISSUE(kt + 1, (kt + 1) & 1);

        uint32_t kb = sb + FKBUF(kt & 1);
        float acc[2][2][4] = {};
#pragma unroll
        for (int k0 = 0; k0 < 64; k0 += 16) {
            uint32_t ah[2][4], al[2][4], bhf[4], blf[4];
#pragma unroll
            for (int mt = 0; mt < 2; mt++) {
                ldsmA(ah[mt], sb + FQ_H, wm * 32 + mt * 16, k0, 144, lane);
                ldsmA(al[mt], sb + FQ_L, wm * 32 + mt * 16, k0, 144, lane);
            }
            ldsmB(bhf, kb,        wn * 16, k0, 144, lane);
            ldsmB(blf, kb + 9216, wn * 16, k0, 144, lane);
#pragma unroll
            for (int mt = 0; mt < 2; mt++) {
                mma3(acc[mt][0], ah[mt], al[mt], &bhf[0], &blf[0]);
                mma3(acc[mt][1], ah[mt], al[mt], &bhf[2], &blf[2]);
            }
        }

        // epilogue: normalize, write attn, split P -> smem
#pragma unroll
        for (int nt = 0; nt < 2; nt++) {
            int cl = wn * 16 + nt * 8 + 2 * (lane & 3);
            int gc = kt * 64 + cl;
            float m0v = (1.0f - mrow[gc]) * (-1e9f);
            float m1v = (1.0f - mrow[gc + 1]) * (-1e9f);
#pragma unroll
            for (int mt = 0; mt < 2; mt++) {
                float* cc = acc[mt][nt];
                int r0 = wm * 32 + mt * 16 + (lane >> 2);
                float e0 = __expf(cc[0] + m0v) * invr[mt][0];
                float e1 = __expf(cc[1] + m1v) * invr[mt][0];
                float e2 = __expf(cc[2] + m0v) * invr[mt][1];
                float e3 = __expf(cc[3] + m1v) * invr[mt][1];
                *(float2*)(Abh + (long)r0 * 2048 + gc)       = make_float2(e0, e1);
                *(float2*)(Abh + (long)(r0 + 8) * 2048 + gc) = make_float2(e2, e3);
                smem_split2(sm + FP_H + r0 * 144 + cl * 2,
                            sm + FP_L + r0 * 144 + cl * 2, e0, e1);
                smem_split2(sm + FP_H + (r0 + 8) * 144 + cl * 2,
                            sm + FP_L + (r0 + 8) * 144 + cl * 2, e2, e3);
            }
        }

        if (kt + 1 < 32) { CPWAIT(1); } else { CPWAIT(0); }
        __syncthreads();                   // V(kt) + P visible

        // O += P · V^T  (P 64x64 @FP, V 64x64 @FV; warp: 32q x 16d)
#pragma unroll
        for (int k0 = 0; k0 < 64; k0 += 16) {
            uint32_t ah[2][4], al[2][4], bhf[4], blf[4];
#pragma unroll
            for (int mt = 0; mt < 2; mt++) {
                ldsmA(ah[mt], sb + FP_H, wm * 32 + mt * 16, k0, 144, lane);
                ldsmA(al[mt], sb + FP_L, wm * 32 + mt * 16, k0, 144, lane);
            }
            ldsmB(bhf, sb + FV_H, wn * 16, k0, 144, lane);
            ldsmB(blf, sb + FV_L, wn * 16, k0, 144, lane);
#pragma unroll
            for (int mt = 0; mt < 2; mt++) {
                mma3(oacc[mt][0], ah[mt], al[mt], &bhf[0], &blf[0]);
                mma3(oacc[mt][1], ah[mt], al[mt], &bhf[2], &blf[2]);
            }
        }
    }

    // write blended split [b, q, h*64+d]
#pragma unroll
    for (int mt = 0; mt < 2; mt++)
#pragma unroll
        for (int nt = 0; nt < 2; nt++) {
            float* cc = oacc[mt][nt];
            long r0 = (long)b * 2048 + qt * 64 + wm * 32 + mt * 16 + (lane >> 2);
            int col = h * 64 + wn * 16 + nt * 8 + 2 * (lane & 3);
            store_split2(Bh, Bl, r0 * 1024 + col, cc[0], cc[1]);
            store_split2(Bh, Bl, (r0 + 8) * 1024 + col, cc[2], cc[3]);
        }
}

// ===========================================================================
extern "C" void kernel_launch(void* const* d_in, const int* in_sizes, int n_in,
                              void* d_out, int out_size) {
    (void)in_sizes; (void)n_in;
    const float* query        = (const float*)d_in[0];
    const float* input_embeds = (const float*)d_in[1];
    const float* mask         = (const float*)d_in[2];
    const float* wq_w = (const float*)d_in[3];
    const float* wq_b = (const float*)d_in[4];
    const float* wk_w = (const float*)d_in[5];
    const float* wk_b = (const float*)d_in[6];
    const float* wv_w = (const float*)d_in[7];
    const float* wv_b = (const float*)d_in[8];
    const float* wo_w = (const float*)d_in[9];
    const float* wo_b = (const float*)d_in[10];
    float* out = (float*)d_out;

    bf16 *qh, *ql, *xh, *xl, *wqh, *wql, *wkh, *wkl, *wvh, *wvl, *woh, *wol;
    bf16 *Qh, *Ql, *Kh, *Kl, *Vh, *Vl, *Vth, *Vtl, *Bh, *Bl;
    float *attn_scratch;
    cudaGetSymbolAddress((void**)&qh, g_qh);   cudaGetSymbolAddress((void**)&ql, g_ql);
    cudaGetSymbolAddress((void**)&xh, g_xh);   cudaGetSymbolAddress((void**)&xl, g_xl);
    cudaGetSymbolAddress((void**)&wqh, g_wqh); cudaGetSymbolAddress((void**)&wql, g_wql);
    cudaGetSymbolAddress((void**)&wkh, g_wkh); cudaGetSymbolAddress((void**)&wkl, g_wkl);
    cudaGetSymbolAddress((void**)&wvh, g_wvh); cudaGetSymbolAddress((void**)&wvl, g_wvl);
    cudaGetSymbolAddress((void**)&woh, g_woh); cudaGetSymbolAddress((void**)&wol, g_wol);
    cudaGetSymbolAddress((void**)&Qh, g_Qh);   cudaGetSymbolAddress((void**)&Ql, g_Ql);
    cudaGetSymbolAddress((void**)&Kh, g_Kh);   cudaGetSymbolAddress((void**)&Kl, g_Kl);
    cudaGetSymbolAddress((void**)&Vh, g_Vh);   cudaGetSymbolAddress((void**)&Vl, g_Vl);
    cudaGetSymbolAddress((void**)&Vth, g_Vth); cudaGetSymbolAddress((void**)&Vtl, g_Vtl);
    cudaGetSymbolAddress((void**)&Bh, g_Bh);   cudaGetSymbolAddress((void**)&Bl, g_Bl);
    cudaGetSymbolAddress((void**)&attn_scratch, g_attn);

    const long OUT_E = 4194304L, ATTN_E = 134217728L;
    float* attn = ((long)out_size >= OUT_E + ATTN_E) ? (out + OUT_E) : attn_scratch;

    const int SM_GEMM = 81920;
    cudaFuncSetAttribute(proj3,      cudaFuncAttributeMaxDynamicSharedMemorySize, SM_GEMM);
    cudaFuncSetAttribute(hgemm_out,  cudaFuncAttributeMaxDynamicSharedMemorySize, SM_GEMM);
    cudaFuncSetAttribute(fused_attn, cudaFuncAttributeMaxDynamicSharedMemorySize, SM_FUSED);

    cvt_all<<<12288, 256>>>(query, input_embeds, wq_w, wk_w, wv_w, wo_w,
                            qh, ql, xh, xl, wqh, wql, wkh, wkl, wvh, wvl, woh, wol);

    proj3<<<dim3(8, 32, 3), 256, SM_GEMM>>>(qh, ql, xh, xl,
                                            wqh, wql, wkh, wkl, wvh, wvl,
                                            wq_b, wk_b, wv_b,
                                            Qh, Ql, Kh, Kl, Vh, Vl);

    vtrans<<<dim3(32, 32), 256>>>(Vh, Vl, Vth, Vtl);

    fused_attn<<<dim3(32, 32), 256, SM_FUSED>>>(Qh, Ql, Kh, Kl, Vth, Vtl, mask,
                                                attn, Bh, Bl);

    hgemm_out<<<dim3(8, 32), 256, SM_GEMM>>>(Bh, Bl, woh, wol, wo_b, out);
}

// round 11
// speedup vs baseline: 1.1418x; 1.0503x over previous
#include <cuda_runtime.h>
#include <cuda_bf16.h>
#include <cuda_fp16.h>
#include <cstdint>

typedef __nv_bfloat16 bf16;

// ---------------------------------------------------------------------------
static __device__ __forceinline__ uint32_t smem_u32(const void* p) {
    uint32_t a;
    asm("{ .reg .u64 t; cvta.to.shared.u64 t, %1; cvt.u32.u64 %0, t; }" : "=r"(a) : "l"(p));
    return a;
}
static __device__ __forceinline__ void mma16816(float* c, const uint32_t* a, const uint32_t* b) {
    asm volatile("mma.sync.aligned.m16n8k16.row.col.f32.bf16.bf16.f32 "
        "{%0,%1,%2,%3}, {%4,%5,%6,%7}, {%8,%9}, {%0,%1,%2,%3};"
        : "+f"(c[0]), "+f"(c[1]), "+f"(c[2]), "+f"(c[3])
        : "r"(a[0]), "r"(a[1]), "r"(a[2]), "r"(a[3]), "r"(b[0]), "r"(b[1]));
}
static __device__ __forceinline__ void mma16816h(float* c, const uint32_t* a, const uint32_t* b) {
    asm volatile("mma.sync.aligned.m16n8k16.row.col.f32.f16.f16.f32 "
        "{%0,%1,%2,%3}, {%4,%5,%6,%7}, {%8,%9}, {%0,%1,%2,%3};"
        : "+f"(c[0]), "+f"(c[1]), "+f"(c[2]), "+f"(c[3])
        : "r"(a[0]), "r"(a[1]), "r"(a[2]), "r"(a[3]), "r"(b[0]), "r"(b[1]));
}
static __device__ __forceinline__ void mma3(float* c, const uint32_t* ah, const uint32_t* al,
                                            const uint32_t* bh, const uint32_t* bl) {
    mma16816(c, ah, bh); mma16816(c, ah, bl); mma16816(c, al, bh);
}
static __device__ __forceinline__ void ldsm4(uint32_t* r, uint32_t a) {
    asm volatile("ldmatrix.sync.aligned.m8n8.x4.shared.b16 {%0,%1,%2,%3}, [%4];"
        : "=r"(r[0]), "=r"(r[1]), "=r"(r[2]), "=r"(r[3]) : "r"(a));
}
static __device__ __forceinline__ void ldsmA(uint32_t* r, uint32_t base, int m0, int k0, int sbytes, int lane) {
    ldsm4(r, base + (uint32_t)((m0 + (lane & 7) + ((lane >> 3) & 1) * 8) * sbytes
                               + (k0 + ((lane >> 4) << 3)) * 2));
}
static __device__ __forceinline__ void ldsmB(uint32_t* r, uint32_t base, int n0, int k0, int sbytes, int lane) {
    ldsm4(r, base + (uint32_t)((n0 + (lane & 7) + ((lane >> 4) << 3)) * sbytes
                               + (k0 + (((lane >> 3) & 1) << 3)) * 2));
}
#define CP16(sm_, gp_) asm volatile("cp.async.cg.shared.global [%0], [%1], 16;" :: "r"(sm_), "l"(gp_))
#define CPCOMMIT()     asm volatile("cp.async.commit_group;")
#define CPWAIT(n)      asm volatile("cp.async.wait_group %0;" :: "n"(n))

static __device__ __forceinline__ void store_split2(bf16* Ch, bf16* Cl, long off, float x, float y) {
    __align__(4) bf16 h[2] = {__float2bfloat16(x), __float2bfloat16(y)};
    __align__(4) bf16 l[2] = {__float2bfloat16(x - __bfloat162float(h[0])),
                              __float2bfloat16(y - __bfloat162float(h[1]))};
    *(uint32_t*)(Ch + off) = *(uint32_t*)h;
    *(uint32_t*)(Cl + off) = *(uint32_t*)l;
}
// pack 2 floats -> fp16x2 -> one 4B smem store
static __device__ __forceinline__ void smem_h2f16(char* p, float x, float y) {
    __half2 h = __floats2half2_rn(x, y);
    *(uint32_t*)p = *(uint32_t*)&h;
}

// ---------------- scratch ----------------
__device__ bf16 g_qh[4194304], g_ql[4194304];
__device__ bf16 g_xh[4194304], g_xl[4194304];
__device__ bf16 g_wqh[1048576], g_wql[1048576];
__device__ bf16 g_wkh[1048576], g_wkl[1048576];
__device__ bf16 g_wvh[1048576], g_wvl[1048576];
__device__ bf16 g_woh[1048576], g_wol[1048576];
__device__ bf16 g_Qh[4194304], g_Ql[4194304];
__device__ bf16 g_Kh[4194304], g_Kl[4194304];
__device__ bf16 g_Vh[4194304], g_Vl[4194304];
__device__ __half g_Vth16[4194304], g_Vtl16[4194304];   // V^T fp16 hi/lo: [bh][64 d][2048 tok]
__device__ bf16 g_Bh[4194304], g_Bl[4194304];
__device__ float g_attn[134217728];

// ---------------- merged fp32 -> bf16 hi/lo for all 6 tensors ----------------
__global__ __launch_bounds__(256) void cvt_all(
    const float* __restrict__ s0, const float* __restrict__ s1,
    const float* __restrict__ s2, const float* __restrict__ s3,
    const float* __restrict__ s4, const float* __restrict__ s5,
    bf16* __restrict__ h0, bf16* __restrict__ l0, bf16* __restrict__ h1, bf16* __restrict__ l1,
    bf16* __restrict__ h2, bf16* __restrict__ l2, bf16* __restrict__ h3, bf16* __restrict__ l3,
    bf16* __restrict__ h4, bf16* __restrict__ l4, bf16* __restrict__ h5, bf16* __restrict__ l5)
{
    long i = (long)blockIdx.x * 256 + threadIdx.x;   // < 3145728
    const float* src; bf16 *h, *l; long li;
    if (i < 1048576)      { src = s0; h = h0; l = l0; li = i; }
    else if (i < 2097152) { src = s1; h = h1; l = l1; li = i - 1048576; }
    else {
        long j = i - 2097152;
        int w = (int)(j >> 18);
        li = j & 262143;
        src = (w == 0) ? s2 : (w == 1) ? s3 : (w == 2) ? s4 : s5;
        h   = (w == 0) ? h2 : (w == 1) ? h3 : (w == 2) ? h4 : h5;
        l   = (w == 0) ? l2 : (w == 1) ? l3 : (w == 2) ? l4 : l5;
    }
    float4 v = ((const float4*)src)[li];
    float f[4] = {v.x, v.y, v.z, v.w};
    __align__(8) bf16 hv[4], lv[4];
#pragma unroll
    for (int j = 0; j < 4; j++) {
        hv[j] = __float2bfloat16(f[j]);
        lv[j] = __float2bfloat16(f[j] - __bfloat162float(hv[j]));
    }
    ((uint2*)h)[li] = *(uint2*)hv;
    ((uint2*)l)[li] = *(uint2*)lv;
}

// ---------------------------------------------------------------------------
// hgemm body: 256 threads, warp grid 4m x 2n, 128x128 tile, BK=32,
// cp.async double-buffered, smem 81920B.
// ---------------------------------------------------------------------------
static __device__ __forceinline__ void hgemm_body(
    const bf16* __restrict__ Ah, const bf16* __restrict__ Al,
    const bf16* __restrict__ Bh, const bf16* __restrict__ Bl,
    const float* __restrict__ bias, float* __restrict__ Cf,
    bf16* __restrict__ Ch, bf16* __restrict__ Cl,
    int K, int lda, int ldb, int ldc, char* sm)
{
    uint32_t sb = smem_u32(sm);
    int t = threadIdx.x, lane = t & 31, wid = t >> 5;
    int wm = wid & 3, wn = wid >> 2;
    long m0 = blockIdx.y * 128, n0 = blockIdx.x * 128;

    const bf16* g0 = Ah + m0 * lda;
    const bf16* g1 = Al + m0 * lda;
    const bf16* g2 = Bh + n0 * ldb;
    const bf16* g3 = Bl + n0 * ldb;

#define G_ISSUE(c_, buf_) do {                                                  \
    int _c = (c_); uint32_t _bs = sb + (buf_) * 40960;                          \
    _Pragma("unroll")                                                           \
    for (int i = 0; i < 8; i++) {                                               \
        const int tile = i >> 1;                                                \
        int w = t + 256 * (i & 1);                                               \
        int row = w >> 2, sg = w & 3;                                           \
        const bf16* gp = (tile == 0 ? g0 : tile == 1 ? g1 : tile == 2 ? g2 : g3)\
            + (long)row * (tile < 2 ? lda : ldb) + _c * 32 + sg * 8;            \
        CP16(_bs + tile * 10240 + row * 80 + sg * 16, gp);                      \
    }                                                                           \
    CPCOMMIT();                                                                 \
} while (0)

    float acc[2][8][4] = {};
    int nc = K >> 5;
    G_ISSUE(0, 0);
    G_ISSUE(1, 1);
    for (int c = 0; c < nc; c++) {
        if (c + 1 < nc) { CPWAIT(1); } else { CPWAIT(0); }
        __syncthreads();
        uint32_t bAh = sb + (c & 1) * 40960, bAl = bAh + 10240;
        uint32_t bBh = bAh + 20480, bBl = bAh + 30720;
#pragma unroll
        for (int k0 = 0; k0 < 32; k0 += 16) {
            uint32_t ah[2][4], al[2][4], bhf[4][4], blf[4][4];
#pragma unroll
            for (int mt = 0; mt < 2; mt++) {
                ldsmA(ah[mt], bAh, wm * 32 + mt * 16, k0, 80, lane);
                ldsmA(al[mt], bAl, wm * 32 + mt * 16, k0, 80, lane);
            }
#pragma unroll
            for (int p = 0; p < 4; p++) {
                ldsmB(bhf[p], bBh, wn * 64 + p * 16, k0, 80, lane);
                ldsmB(blf[p], bBl, wn * 64 + p * 16, k0, 80, lane);
            }
#pragma unroll
            for (int mt = 0; mt < 2; mt++)
#pragma unroll
                for (int p = 0; p < 4; p++) {
                    mma3(acc[mt][p * 2],     ah[mt], al[mt], &bhf[p][0], &blf[p][0]);
                    mma3(acc[mt][p * 2 + 1], ah[mt], al[mt], &bhf[p][2], &blf[p][2]);
                }
        }
        __syncthreads();
        if (c + 2 < nc) G_ISSUE(c + 2, c & 1);
    }
#undef G_ISSUE

#pragma unroll
    for (int mt = 0; mt < 2; mt++)
#pragma unroll
        for (int nt = 0; nt < 8; nt++) {
            float* cc = acc[mt][nt];
            long r0 = m0 + wm * 32 + mt * 16 + (lane >> 2);
            int col = (int)n0 + wn * 64 + nt * 8 + 2 * (lane & 3);
            float b0 = bias[col], b1 = bias[col + 1];
            float f0 = cc[0] + b0, f1 = cc[1] + b1, f2 = cc[2] + b0, f3 = cc[3] + b1;
            if (Cf) {
                *(float2*)(Cf + r0 * ldc + col) = make_float2(f0, f1);
                *(float2*)(Cf + (r0 + 8) * ldc + col) = make_float2(f2, f3);
            }
            if (Ch) {
                store_split2(Ch, Cl, r0 * ldc + col, f0, f1);
                store_split2(Ch, Cl, (r0 + 8) * ldc + col, f2, f3);
            }
        }
}

// merged Q/K/V projections
__global__ __launch_bounds__(256) void proj3(
    const bf16* __restrict__ qh, const bf16* __restrict__ ql,
    const bf16* __restrict__ xh, const bf16* __restrict__ xl,
    const bf16* __restrict__ wqh, const bf16* __restrict__ wql,
    const bf16* __restrict__ wkh, const bf16* __restrict__ wkl,
    const bf16* __restrict__ wvh, const bf16* __restrict__ wvl,
    const float* __restrict__ bq, const float* __restrict__ bk, const float* __restrict__ bv,
    bf16* __restrict__ Qh, bf16* __restrict__ Ql,
    bf16* __restrict__ Kh, bf16* __restrict__ Kl,
    bf16* __restrict__ Vh, bf16* __restrict__ Vl)
{
    extern __shared__ char sm[];
    int z = blockIdx.z;
    const bf16* Ah = (z == 0) ? qh : xh;
    const bf16* Al = (z == 0) ? ql : xl;
    const bf16* Bh = (z == 0) ? wqh : (z == 1) ? wkh : wvh;
    const bf16* Bl = (z == 0) ? wql : (z == 1) ? wkl : wvl;
    const float* bias = (z == 0) ? bq : (z == 1) ? bk : bv;
    bf16* Ch = (z == 0) ? Qh : (z == 1) ? Kh : Vh;
    bf16* Cl = (z == 0) ? Ql : (z == 1) ? Kl : Vl;
    hgemm_body(Ah, Al, Bh, Bl, bias, nullptr, Ch, Cl, 1024, 1024, 1024, 1024, sm);
}

__global__ __launch_bounds__(256) void hgemm_out(
    const bf16* __restrict__ Ah, const bf16* __restrict__ Al,
    const bf16* __restrict__ Bh, const bf16* __restrict__ Bl,
    const float* __restrict__ bias, float* __restrict__ Cf)
{
    extern __shared__ char sm[];
    hgemm_body(Ah, Al, Bh, Bl, bias, Cf, nullptr, nullptr, 1024, 1024, 1024, 1024, sm);
}

// ---------------------------------------------------------------------------
// vtrans: V bf16 hi+lo [4096 tok,1024] -> per (b,h) [64 d][2048 tok],
// reconstruct fp32 and emit fp16 hi/lo split.
// ---------------------------------------------------------------------------
__global__ __launch_bounds__(256) void vtrans(
    const bf16* __restrict__ Vh, const bf16* __restrict__ Vl,
    __half* __restrict__ Th, __half* __restrict__ Tl) {
    __shared__ bf16 sh[64][72], sl[64][72];
    int t = threadIdx.x, tt = blockIdx.x, bh = blockIdx.y;
    int b = bh >> 4, h = bh & 15;
    const bf16* srch = Vh + ((long)b * 2048 + tt * 64) * 1024 + h * 64;
    const bf16* srcl = Vl + ((long)b * 2048 + tt * 64) * 1024 + h * 64;
#pragma unroll
    for (int i = 0; i < 2; i++) {
        int s = t + 256 * i, row = s >> 3, seg = s & 7;
        *(uint4*)&sh[row][seg * 8] = *(const uint4*)(srch + (long)row * 1024 + seg * 8);
        *(uint4*)&sl[row][seg * 8] = *(const uint4*)(srcl + (long)row * 1024 + seg * 8);
    }
    __syncthreads();
    __half* dh = Th + (long)bh * 64 * 2048 + tt * 64;
    __half* dl = Tl + (long)bh * 64 * 2048 + tt * 64;
#pragma unroll
    for (int i = 0; i < 2; i++) {
        int s = t + 256 * i, d = s >> 3, seg = s & 7;
        __align__(16) __half th[8], tl[8];
#pragma unroll
        for (int j = 0; j < 8; j++) {
            float f = __bfloat162float(sh[seg * 8 + j][d]) + __bfloat162float(sl[seg * 8 + j][d]);
            __half hv = __float2half_rn(f);
            th[j] = hv;
            tl[j] = __float2half_rn(f - __half2float(hv));
        }
        *(uint4*)(dh + (long)d * 2048 + seg * 8) = *(uint4*)th;
        *(uint4*)(dl + (long)d * 2048 + seg * 8) = *(uint4*)tl;
    }
}

// ---------------------------------------------------------------------------
// fused_attn: 256 threads, 64-q tile, 64-wide K tiles, 2 CTAs/SM.
// QK: bf16 3-product split. PV: P fp16 single x V fp16 hi/lo (2-product).
// smem (bytes), tiles stride 144:
//   Q hi @0, Q lo @9216
//   K buf0 @18432 (hi,lo), buf1 @36864
//   P fp16 @55296 (9216)
//   V fp16 hi @64512, lo @73728 (9216 each)
//   part @82944 (256 f), invs @83968 (64 f) -> total 84224 -> 2 CTAs/SM
// ---------------------------------------------------------------------------
#define FQ_H  0
#define FQ_L  9216
#define FKBUF(b) (18432 + (b) * 18432)
#define FP_H  55296
#define FV_H  64512
#define FV_L  73728
#define FPART 82944
#define FINVS 83968
#define SM_FUSED 84224

__global__ __launch_bounds__(256, 2) void fused_attn(
    const bf16* __restrict__ Qh, const bf16* __restrict__ Ql,
    const bf16* __restrict__ Kh, const bf16* __restrict__ Kl,
    const __half* __restrict__ Vth, const __half* __restrict__ Vtl,
    const float* __restrict__ mask,
    float* __restrict__ A, bf16* __restrict__ Bh, bf16* __restrict__ Bl)
{
    extern __shared__ char sm[];
    uint32_t sb = smem_u32(sm);
    int t = threadIdx.x, lane = t & 31, wid = t >> 5;
    int wm = wid & 1, wn = wid >> 1;          // 2m x 4n; warp tile 32q x 16k
    int qt = blockIdx.x, bh = blockIdx.y;     // qt: 64-row stripe
    int b = bh >> 4, h = bh & 15;

    const bf16* qh = Qh + ((long)b * 2048 + qt * 64) * 1024 + h * 64;
    const bf16* ql = Ql + ((long)b * 2048 + qt * 64) * 1024 + h * 64;
    const bf16* kh = Kh + (long)b * 2048 * 1024 + h * 64;
    const bf16* kl = Kl + (long)b * 2048 * 1024 + h * 64;
    const __half* vth = Vth + (long)bh * 64 * 2048;
    const __half* vtl = Vtl + (long)bh * 64 * 2048;
    float* Abh = A + ((long)bh * 2048 + qt * 64) * 2048;
    const float* mrow = mask + (long)b * 2048;

    float* part = (float*)(sm + FPART);
    float* invs = (float*)(sm + FINVS);

#define KISSUE(kt_, buf_) do {                                                   \
    int _kt = (kt_); uint32_t _kb = sb + FKBUF(buf_);                            \
    _Pragma("unroll")                                                            \
    for (int i = 0; i < 4; i++) {                                                \
        int w = t + 256 * i;                                                     \
        int tile = w >> 9, inner = w & 511;                                      \
        int row = inner >> 3, sg = inner & 7;                                    \
        const bf16* src = (tile ? kl : kh) + (long)(_kt * 64 + row) * 1024 + sg * 8; \
        CP16(_kb + tile * 9216 + row * 144 + sg * 16, src);                      \
    }                                                                            \
    CPCOMMIT();                                                                  \
} while (0)

// V fp16 hi+lo tile kt: 2 tiles x 64 rows x 8 segs = 1024 units, 4/thread
#define VISSUE(kt_) do {                                                         \
    int _kt = (kt_);                                                             \
    _Pragma("unroll")                                                            \
    for (int i = 0; i < 4; i++) {                                                \
        int w = t + 256 * i;                                                     \
        int tile = w >> 9, inner = w & 511;                                      \
        int row = inner >> 3, sg = inner & 7;                                    \
        const __half* src = (tile ? vtl : vth) + (long)row * 2048 + _kt * 64 + sg * 8; \
        CP16(sb + (tile ? FV_L : FV_H) + row * 144 + sg * 16, src);              \
    }                                                                            \
    CPCOMMIT();                                                                  \
} while (0)

    // prologue: K(0) async, Q tiles plain
    KISSUE(0, 0);
#pragma unroll
    for (int i = 0; i < 4; i++) {
        int w = t + 256 * i;
        int tile = w >> 9, inner = w & 511;
        int row = inner >> 3, sg = inner & 7;
        const bf16* src = (tile ? ql : qh) + (long)row * 1024 + sg * 8;
        *(uint4*)(sm + (tile ? FQ_L : FQ_H) + row * 144 + sg * 16) = *(const uint4*)src;
    }

    // ---------------- pass A: rowsum only ----------------
    float rs[4] = {0.f, 0.f, 0.f, 0.f};
    for (int kt = 0; kt < 32; kt++) {
        CPWAIT(0);
        __syncthreads();
        if (kt + 1 < 32) KISSUE(kt + 1, (kt + 1) & 1);

        uint32_t kb = sb + FKBUF(kt & 1);
        float acc[2][2][4] = {};
#pragma unroll
        for (int k0 = 0; k0 < 64; k0 += 16) {
            uint32_t ah[2][4], al[2][4], bhf[4], blf[4];
#pragma unroll
            for (int mt = 0; mt < 2; mt++) {
                ldsmA(ah[mt], sb + FQ_H, wm * 32 + mt * 16, k0, 144, lane);
                ldsmA(al[mt], sb + FQ_L, wm * 32 + mt * 16, k0, 144, lane);
            }
            ldsmB(bhf, kb,        wn * 16, k0, 144, lane);
            ldsmB(blf, kb + 9216, wn * 16, k0, 144, lane);
#pragma unroll
            for (int mt = 0; mt < 2; mt++) {
                mma3(acc[mt][0], ah[mt], al[mt], &bhf[0], &blf[0]);
                mma3(acc[mt][1], ah[mt], al[mt], &bhf[2], &blf[2]);
            }
        }
#pragma unroll
        for (int nt = 0; nt < 2; nt++) {
            int cl = kt * 64 + wn * 16 + nt * 8 + 2 * (lane & 3);
            float m0v = (1.0f - mrow[cl]) * (-1e9f);
            float m1v = (1.0f - mrow[cl + 1]) * (-1e9f);
#pragma unroll
            for (int mt = 0; mt < 2; mt++) {
                float* cc = acc[mt][nt];
                rs[mt * 2 + 0] += __expf(cc[0] + m0v) + __expf(cc[1] + m1v);
                rs[mt * 2 + 1] += __expf(cc[2] + m0v) + __expf(cc[3] + m1v);
            }
        }
    }

    KISSUE(0, 0);     // K(0) for pass B

    // reduce rowsum -> invs[64]
#pragma unroll
    for (int i = 0; i < 4; i++) {
        rs[i] += __shfl_xor_sync(0xffffffffu, rs[i], 1);
        rs[i] += __shfl_xor_sync(0xffffffffu, rs[i], 2);
    }
    __syncthreads();
    if ((lane & 3) == 0) {
#pragma unroll
        for (int mt = 0; mt < 2; mt++)
#pragma unroll
            for (int hf = 0; hf < 2; hf++)
                part[wn * 64 + wm * 32 + mt * 16 + hf * 8 + (lane >> 2)] = rs[mt * 2 + hf];
    }
    __syncthreads();
    if (t < 64)
        invs[t] = 1.0f / (part[t] + part[64 + t] + part[128 + t] + part[192 + t]);
    __syncthreads();

    float invr[2][2];
#pragma unroll
    for (int mt = 0; mt < 2; mt++) {
        invr[mt][0] = invs[wm * 32 + mt * 16 + (lane >> 2)];
        invr[mt][1] = invs[wm * 32 + mt * 16 + 8 + (lane >> 2)];
    }

    // ---------------- pass B ----------------
    float oacc[2][2][4] = {};
    for (int kt = 0; kt < 32; kt++) {
        CPWAIT(0);
        __syncthreads();                   // K(kt) ready; prior P/V reads done
        VISSUE(kt);                        // V first (released by wait_group 1)
        if (kt + 1 < 32) KISSUE(kt + 1, (kt + 1) & 1);

        uint32_t kb = sb + FKBUF(kt & 1);
        float acc[2][2][4] = {};
#pragma unroll
        for (int k0 = 0; k0 < 64; k0 += 16) {
            uint32_t ah[2][4], al[2][4], bhf[4], blf[4];
#pragma unroll
            for (int mt = 0; mt < 2; mt++) {
                ldsmA(ah[mt], sb + FQ_H, wm * 32 + mt * 16, k0, 144, lane);
                ldsmA(al[mt], sb + FQ_L, wm * 32 + mt * 16, k0, 144, lane);
            }
            ldsmB(bhf, kb,        wn * 16, k0, 144, lane);
            ldsmB(blf, kb + 9216, wn * 16, k0, 144, lane);
#pragma unroll
            for (int mt = 0; mt < 2; mt++) {
                mma3(acc[mt][0], ah[mt], al[mt], &bhf[0], &blf[0]);
                mma3(acc[mt][1], ah[mt], al[mt], &bhf[2], &blf[2]);
            }
        }

        // epilogue: normalize, write attn (fp32 exact), pack P fp16 -> smem
#pragma unroll
        for (int nt = 0; nt < 2; nt++) {
            int cl = wn * 16 + nt * 8 + 2 * (lane & 3);
            int gc = kt * 64 + cl;
            float m0v = (1.0f - mrow[gc]) * (-1e9f);
            float m1v = (1.0f - mrow[gc + 1]) * (-1e9f);
#pragma unroll
            for (int mt = 0; mt < 2; mt++) {
                float* cc = acc[mt][nt];
                int r0 = wm * 32 + mt * 16 + (lane >> 2);
                float e0 = __expf(cc[0] + m0v) * invr[mt][0];
                float e1 = __expf(cc[1] + m1v) * invr[mt][0];
                float e2 = __expf(cc[2] + m0v) * invr[mt][1];
                float e3 = __expf(cc[3] + m1v) * invr[mt][1];
                *(float2*)(Abh + (long)r0 * 2048 + gc)       = make_float2(e0, e1);
                *(float2*)(Abh + (long)(r0 + 8) * 2048 + gc) = make_float2(e2, e3);
                smem_h2f16(sm + FP_H + r0 * 144 + cl * 2, e0, e1);
                smem_h2f16(sm + FP_H + (r0 + 8) * 144 + cl * 2, e2, e3);
            }
        }

        if (kt + 1 < 32) { CPWAIT(1); } else { CPWAIT(0); }
        __syncthreads();                   // V(kt) + P visible

        // O += P(fp16) · (Vh + Vl)^T  (2-product fp16)
#pragma unroll
        for (int k0 = 0; k0 < 64; k0 += 16) {
            uint32_t ah[2][4], bhf[4], blf[4];
#pragma unroll
            for (int mt = 0; mt < 2; mt++)
                ldsmA(ah[mt], sb + FP_H, wm * 32 + mt * 16, k0, 144, lane);
            ldsmB(bhf, sb + FV_H, wn * 16, k0, 144, lane);
            ldsmB(blf, sb + FV_L, wn * 16, k0, 144, lane);
#pragma unroll
            for (int mt = 0; mt < 2; mt++) {
                mma16816h(oacc[mt][0], ah[mt], &bhf[0]);
                mma16816h(oacc[mt][0], ah[mt], &blf[0]);
                mma16816h(oacc[mt][1], ah[mt], &bhf[2]);
                mma16816h(oacc[mt][1], ah[mt], &blf[2]);
            }
        }
    }

    // write blended split [b, q, h*64+d]
#pragma unroll
    for (int mt = 0; mt < 2; mt++)
#pragma unroll
        for (int nt = 0; nt < 2; nt++) {
            float* cc = oacc[mt][nt];
            long r0 = (long)b * 2048 + qt * 64 + wm * 32 + mt * 16 + (lane >> 2);
            int col = h * 64 + wn * 16 + nt * 8 + 2 * (lane & 3);
            store_split2(Bh, Bl, r0 * 1024 + col, cc[0], cc[1]);
            store_split2(Bh, Bl, (r0 + 8) * 1024 + col, cc[2], cc[3]);
        }
}

// ===========================================================================
extern "C" void kernel_launch(void* const* d_in, const int* in_sizes, int n_in,
                              void* d_out, int out_size) {
    (void)in_sizes; (void)n_in;
    const float* query        = (const float*)d_in[0];
    const float* input_embeds = (const float*)d_in[1];
    const float* mask         = (const float*)d_in[2];
    const float* wq_w = (const float*)d_in[3];
    const float* wq_b = (const float*)d_in[4];
    const float* wk_w = (const float*)d_in[5];
    const float* wk_b = (const float*)d_in[6];
    const float* wv_w = (const float*)d_in[7];
    const float* wv_b = (const float*)d_in[8];
    const float* wo_w = (const float*)d_in[9];
    const float* wo_b = (const float*)d_in[10];
    float* out = (float*)d_out;

    bf16 *qh, *ql, *xh, *xl, *wqh, *wql, *wkh, *wkl, *wvh, *wvl, *woh, *wol;
    bf16 *Qh, *Ql, *Kh, *Kl, *Vh, *Vl, *Bh, *Bl;
    __half *Vth16, *Vtl16;
    float *attn_scratch;
    cudaGetSymbolAddress((void**)&qh, g_qh);   cudaGetSymbolAddress((void**)&ql, g_ql);
    cudaGetSymbolAddress((void**)&xh, g_xh);   cudaGetSymbolAddress((void**)&xl, g_xl);
    cudaGetSymbolAddress((void**)&wqh, g_wqh); cudaGetSymbolAddress((void**)&wql, g_wql);
    cudaGetSymbolAddress((void**)&wkh, g_wkh); cudaGetSymbolAddress((void**)&wkl, g_wkl);
    cudaGetSymbolAddress((void**)&wvh, g_wvh); cudaGetSymbolAddress((void**)&wvl, g_wvl);
    cudaGetSymbolAddress((void**)&woh, g_woh); cudaGetSymbolAddress((void**)&wol, g_wol);
    cudaGetSymbolAddress((void**)&Qh, g_Qh);   cudaGetSymbolAddress((void**)&Ql, g_Ql);
    cudaGetSymbolAddress((void**)&Kh, g_Kh);   cudaGetSymbolAddress((void**)&Kl, g_Kl);
    cudaGetSymbolAddress((void**)&Vh, g_Vh);   cudaGetSymbolAddress((void**)&Vl, g_Vl);
    cudaGetSymbolAddress((void**)&Vth16, g_Vth16);
    cudaGetSymbolAddress((void**)&Vtl16, g_Vtl16);
    cudaGetSymbolAddress((void**)&Bh, g_Bh);   cudaGetSymbolAddress((void**)&Bl, g_Bl);
    cudaGetSymbolAddress((void**)&attn_scratch, g_attn);

    const long OUT_E = 4194304L, ATTN_E = 134217728L;
    float* attn = ((long)out_size >= OUT_E + ATTN_E) ? (out + OUT_E) : attn_scratch;

    const int SM_GEMM = 81920;
    cudaFuncSetAttribute(proj3,      cudaFuncAttributeMaxDynamicSharedMemorySize, SM_GEMM);
    cudaFuncSetAttribute(hgemm_out,  cudaFuncAttributeMaxDynamicSharedMemorySize, SM_GEMM);
    cudaFuncSetAttribute(fused_attn, cudaFuncAttributeMaxDynamicSharedMemorySize, SM_FUSED);

    cvt_all<<<12288, 256>>>(query, input_embeds, wq_w, wk_w, wv_w, wo_w,
                            qh, ql, xh, xl, wqh, wql, wkh, wkl, wvh, wvl, woh, wol);

    proj3<<<dim3(8, 32, 3), 256, SM_GEMM>>>(qh, ql, xh, xl,
                                            wqh, wql, wkh, wkl, wvh, wvl,
                                            wq_b, wk_b, wv_b,
                                            Qh, Ql, Kh, Kl, Vh, Vl);

    vtrans<<<dim3(32, 32), 256>>>(Vh, Vl, Vth16, Vtl16);

    fused_attn<<<dim3(32, 32), 256, SM_FUSED>>>(Qh, Ql, Kh, Kl, Vth16, Vtl16, mask,
                                                attn, Bh, Bl);

    hgemm_out<<<dim3(8, 32), 256, SM_GEMM>>>(Bh, Bl, woh, wol, wo_b, out);
}

// round 12
// speedup vs baseline: 1.1738x; 1.0281x over previous
#include <cuda_runtime.h>
#include <cuda_bf16.h>
#include <cuda_fp16.h>
#include <cstdint>

typedef __nv_bfloat16 bf16;

// ---------------------------------------------------------------------------
static __device__ __forceinline__ uint32_t smem_u32(const void* p) {
    uint32_t a;
    asm("{ .reg .u64 t; cvta.to.shared.u64 t, %1; cvt.u32.u64 %0, t; }" : "=r"(a) : "l"(p));
    return a;
}
static __device__ __forceinline__ void mma16816(float* c, const uint32_t* a, const uint32_t* b) {
    asm volatile("mma.sync.aligned.m16n8k16.row.col.f32.bf16.bf16.f32 "
        "{%0,%1,%2,%3}, {%4,%5,%6,%7}, {%8,%9}, {%0,%1,%2,%3};"
        : "+f"(c[0]), "+f"(c[1]), "+f"(c[2]), "+f"(c[3])
        : "r"(a[0]), "r"(a[1]), "r"(a[2]), "r"(a[3]), "r"(b[0]), "r"(b[1]));
}
static __device__ __forceinline__ void mma16816h(float* c, const uint32_t* a, const uint32_t* b) {
    asm volatile("mma.sync.aligned.m16n8k16.row.col.f32.f16.f16.f32 "
        "{%0,%1,%2,%3}, {%4,%5,%6,%7}, {%8,%9}, {%0,%1,%2,%3};"
        : "+f"(c[0]), "+f"(c[1]), "+f"(c[2]), "+f"(c[3])
        : "r"(a[0]), "r"(a[1]), "r"(a[2]), "r"(a[3]), "r"(b[0]), "r"(b[1]));
}
static __device__ __forceinline__ void mma3(float* c, const uint32_t* ah, const uint32_t* al,
                                            const uint32_t* bh, const uint32_t* bl) {
    mma16816(c, ah, bh); mma16816(c, ah, bl); mma16816(c, al, bh);
}
static __device__ __forceinline__ void ldsm4(uint32_t* r, uint32_t a) {
    asm volatile("ldmatrix.sync.aligned.m8n8.x4.shared.b16 {%0,%1,%2,%3}, [%4];"
        : "=r"(r[0]), "=r"(r[1]), "=r"(r[2]), "=r"(r[3]) : "r"(a));
}
static __device__ __forceinline__ void ldsmA(uint32_t* r, uint32_t base, int m0, int k0, int sbytes, int lane) {
    ldsm4(r, base + (uint32_t)((m0 + (lane & 7) + ((lane >> 3) & 1) * 8) * sbytes
                               + (k0 + ((lane >> 4) << 3)) * 2));
}
static __device__ __forceinline__ void ldsmB(uint32_t* r, uint32_t base, int n0, int k0, int sbytes, int lane) {
    ldsm4(r, base + (uint32_t)((n0 + (lane & 7) + ((lane >> 4) << 3)) * sbytes
                               + (k0 + (((lane >> 3) & 1) << 3)) * 2));
}
#define CP16(sm_, gp_) asm volatile("cp.async.cg.shared.global [%0], [%1], 16;" :: "r"(sm_), "l"(gp_))
#define CPCOMMIT()     asm volatile("cp.async.commit_group;")
#define CPWAIT(n)      asm volatile("cp.async.wait_group %0;" :: "n"(n))

static __device__ __forceinline__ void store_split2(bf16* Ch, bf16* Cl, long off, float x, float y) {
    __align__(4) bf16 h[2] = {__float2bfloat16(x), __float2bfloat16(y)};
    __align__(4) bf16 l[2] = {__float2bfloat16(x - __bfloat162float(h[0])),
                              __float2bfloat16(y - __bfloat162float(h[1]))};
    *(uint32_t*)(Ch + off) = *(uint32_t*)h;
    *(uint32_t*)(Cl + off) = *(uint32_t*)l;
}
static __device__ __forceinline__ void smem_h2f16(char* p, float x, float y) {
    __half2 h = __floats2half2_rn(x, y);
    *(uint32_t*)p = *(uint32_t*)&h;
}

// ---------------- scratch ----------------
__device__ bf16 g_qh[4194304], g_ql[4194304];
__device__ bf16 g_xh[4194304], g_xl[4194304];
__device__ bf16 g_wqh[1048576], g_wql[1048576];
__device__ bf16 g_wkh[1048576], g_wkl[1048576];
__device__ bf16 g_wvh[1048576], g_wvl[1048576];
__device__ bf16 g_woh[1048576], g_wol[1048576];
__device__ bf16 g_Qh[4194304], g_Ql[4194304];
__device__ bf16 g_Kh[4194304], g_Kl[4194304];
__device__ bf16 g_Vh[4194304], g_Vl[4194304];
__device__ __half g_Vth16[4194304], g_Vtl16[4194304];   // V^T fp16 hi/lo
__device__ bf16 g_Bh[4194304], g_Bl[4194304];
__device__ float g_attn[134217728];

// ---------------- merged fp32 -> bf16 hi/lo for all 6 tensors ----------------
__global__ __launch_bounds__(256) void cvt_all(
    const float* __restrict__ s0, const float* __restrict__ s1,
    const float* __restrict__ s2, const float* __restrict__ s3,
    const float* __restrict__ s4, const float* __restrict__ s5,
    bf16* __restrict__ h0, bf16* __restrict__ l0, bf16* __restrict__ h1, bf16* __restrict__ l1,
    bf16* __restrict__ h2, bf16* __restrict__ l2, bf16* __restrict__ h3, bf16* __restrict__ l3,
    bf16* __restrict__ h4, bf16* __restrict__ l4, bf16* __restrict__ h5, bf16* __restrict__ l5)
{
    long i = (long)blockIdx.x * 256 + threadIdx.x;   // < 3145728
    const float* src; bf16 *h, *l; long li;
    if (i < 1048576)      { src = s0; h = h0; l = l0; li = i; }
    else if (i < 2097152) { src = s1; h = h1; l = l1; li = i - 1048576; }
    else {
        long j = i - 2097152;
        int w = (int)(j >> 18);
        li = j & 262143;
        src = (w == 0) ? s2 : (w == 1) ? s3 : (w == 2) ? s4 : s5;
        h   = (w == 0) ? h2 : (w == 1) ? h3 : (w == 2) ? h4 : h5;
        l   = (w == 0) ? l2 : (w == 1) ? l3 : (w == 2) ? l4 : l5;
    }
    float4 v = ((const float4*)src)[li];
    float f[4] = {v.x, v.y, v.z, v.w};
    __align__(8) bf16 hv[4], lv[4];
#pragma unroll
    for (int j = 0; j < 4; j++) {
        hv[j] = __float2bfloat16(f[j]);
        lv[j] = __float2bfloat16(f[j] - __bfloat162float(hv[j]));
    }
    ((uint2*)h)[li] = *(uint2*)hv;
    ((uint2*)l)[li] = *(uint2*)lv;
}

// ---------------------------------------------------------------------------
// hgemm body (unchanged, proven): 256 threads, 4m x 2n, 128x128, BK=32
// ---------------------------------------------------------------------------
static __device__ __forceinline__ void hgemm_body(
    const bf16* __restrict__ Ah, const bf16* __restrict__ Al,
    const bf16* __restrict__ Bh, const bf16* __restrict__ Bl,
    const float* __restrict__ bias, float* __restrict__ Cf,
    bf16* __restrict__ Ch, bf16* __restrict__ Cl,
    int K, int lda, int ldb, int ldc, char* sm)
{
    uint32_t sb = smem_u32(sm);
    int t = threadIdx.x, lane = t & 31, wid = t >> 5;
    int wm = wid & 3, wn = wid >> 2;
    long m0 = blockIdx.y * 128, n0 = blockIdx.x * 128;

    const bf16* g0 = Ah + m0 * lda;
    const bf16* g1 = Al + m0 * lda;
    const bf16* g2 = Bh + n0 * ldb;
    const bf16* g3 = Bl + n0 * ldb;

#define G_ISSUE(c_, buf_) do {                                                  \
    int _c = (c_); uint32_t _bs = sb + (buf_) * 40960;                          \
    _Pragma("unroll")                                                           \
    for (int i = 0; i < 8; i++) {                                               \
        const int tile = i >> 1;                                                \
        int w = t + 256 * (i & 1);                                               \
        int row = w >> 2, sg = w & 3;                                           \
        const bf16* gp = (tile == 0 ? g0 : tile == 1 ? g1 : tile == 2 ? g2 : g3)\
            + (long)row * (tile < 2 ? lda : ldb) + _c * 32 + sg * 8;            \
        CP16(_bs + tile * 10240 + row * 80 + sg * 16, gp);                      \
    }                                                                           \
    CPCOMMIT();                                                                 \
} while (0)

    float acc[2][8][4] = {};
    int nc = K >> 5;
    G_ISSUE(0, 0);
    G_ISSUE(1, 1);
    for (int c = 0; c < nc; c++) {
        if (c + 1 < nc) { CPWAIT(1); } else { CPWAIT(0); }
        __syncthreads();
        uint32_t bAh = sb + (c & 1) * 40960, bAl = bAh + 10240;
        uint32_t bBh = bAh + 20480, bBl = bAh + 30720;
#pragma unroll
        for (int k0 = 0; k0 < 32; k0 += 16) {
            uint32_t ah[2][4], al[2][4], bhf[4][4], blf[4][4];
#pragma unroll
            for (int mt = 0; mt < 2; mt++) {
                ldsmA(ah[mt], bAh, wm * 32 + mt * 16, k0, 80, lane);
                ldsmA(al[mt], bAl, wm * 32 + mt * 16, k0, 80, lane);
            }
#pragma unroll
            for (int p = 0; p < 4; p++) {
                ldsmB(bhf[p], bBh, wn * 64 + p * 16, k0, 80, lane);
                ldsmB(blf[p], bBl, wn * 64 + p * 16, k0, 80, lane);
            }
#pragma unroll
            for (int mt = 0; mt < 2; mt++)
#pragma unroll
                for (int p = 0; p < 4; p++) {
                    mma3(acc[mt][p * 2],     ah[mt], al[mt], &bhf[p][0], &blf[p][0]);
                    mma3(acc[mt][p * 2 + 1], ah[mt], al[mt], &bhf[p][2], &blf[p][2]);
                }
        }
        __syncthreads();
        if (c + 2 < nc) G_ISSUE(c + 2, c & 1);
    }
#undef G_ISSUE

#pragma unroll
    for (int mt = 0; mt < 2; mt++)
#pragma unroll
        for (int nt = 0; nt < 8; nt++) {
            float* cc = acc[mt][nt];
            long r0 = m0 + wm * 32 + mt * 16 + (lane >> 2);
            int col = (int)n0 + wn * 64 + nt * 8 + 2 * (lane & 3);
            float b0 = bias[col], b1 = bias[col + 1];
            float f0 = cc[0] + b0, f1 = cc[1] + b1, f2 = cc[2] + b0, f3 = cc[3] + b1;
            if (Cf) {
                *(float2*)(Cf + r0 * ldc + col) = make_float2(f0, f1);
                *(float2*)(Cf + (r0 + 8) * ldc + col) = make_float2(f2, f3);
            }
            if (Ch) {
                store_split2(Ch, Cl, r0 * ldc + col, f0, f1);
                store_split2(Ch, Cl, (r0 + 8) * ldc + col, f2, f3);
            }
        }
}

__global__ __launch_bounds__(256) void proj3(
    const bf16* __restrict__ qh, const bf16* __restrict__ ql,
    const bf16* __restrict__ xh, const bf16* __restrict__ xl,
    const bf16* __restrict__ wqh, const bf16* __restrict__ wql,
    const bf16* __restrict__ wkh, const bf16* __restrict__ wkl,
    const bf16* __restrict__ wvh, const bf16* __restrict__ wvl,
    const float* __restrict__ bq, const float* __restrict__ bk, const float* __restrict__ bv,
    bf16* __restrict__ Qh, bf16* __restrict__ Ql,
    bf16* __restrict__ Kh, bf16* __restrict__ Kl,
    bf16* __restrict__ Vh, bf16* __restrict__ Vl)
{
    extern __shared__ char sm[];
    int z = blockIdx.z;
    const bf16* Ah = (z == 0) ? qh : xh;
    const bf16* Al = (z == 0) ? ql : xl;
    const bf16* Bh = (z == 0) ? wqh : (z == 1) ? wkh : wvh;
    const bf16* Bl = (z == 0) ? wql : (z == 1) ? wkl : wvl;
    const float* bias = (z == 0) ? bq : (z == 1) ? bk : bv;
    bf16* Ch = (z == 0) ? Qh : (z == 1) ? Kh : Vh;
    bf16* Cl = (z == 0) ? Ql : (z == 1) ? Kl : Vl;
    hgemm_body(Ah, Al, Bh, Bl, bias, nullptr, Ch, Cl, 1024, 1024, 1024, 1024, sm);
}

__global__ __launch_bounds__(256) void hgemm_out(
    const bf16* __restrict__ Ah, const bf16* __restrict__ Al,
    const bf16* __restrict__ Bh, const bf16* __restrict__ Bl,
    const float* __restrict__ bias, float* __restrict__ Cf)
{
    extern __shared__ char sm[];
    hgemm_body(Ah, Al, Bh, Bl, bias, Cf, nullptr, nullptr, 1024, 1024, 1024, 1024, sm);
}

// ---------------------------------------------------------------------------
// vtrans: V bf16 hi+lo -> per (b,h) [64 d][2048 tok], fp16 hi/lo split
// ---------------------------------------------------------------------------
__global__ __launch_bounds__(256) void vtrans(
    const bf16* __restrict__ Vh, const bf16* __restrict__ Vl,
    __half* __restrict__ Th, __half* __restrict__ Tl) {
    __shared__ bf16 sh[64][72], sl[64][72];
    int t = threadIdx.x, tt = blockIdx.x, bh = blockIdx.y;
    int b = bh >> 4, h = bh & 15;
    const bf16* srch = Vh + ((long)b * 2048 + tt * 64) * 1024 + h * 64;
    const bf16* srcl = Vl + ((long)b * 2048 + tt * 64) * 1024 + h * 64;
#pragma unroll
    for (int i = 0; i < 2; i++) {
        int s = t + 256 * i, row = s >> 3, seg = s & 7;
        *(uint4*)&sh[row][seg * 8] = *(const uint4*)(srch + (long)row * 1024 + seg * 8);
        *(uint4*)&sl[row][seg * 8] = *(const uint4*)(srcl + (long)row * 1024 + seg * 8);
    }
    __syncthreads();
    __half* dh = Th + (long)bh * 64 * 2048 + tt * 64;
    __half* dl = Tl + (long)bh * 64 * 2048 + tt * 64;
#pragma unroll
    for (int i = 0; i < 2; i++) {
        int s = t + 256 * i, d = s >> 3, seg = s & 7;
        __align__(16) __half th[8], tl[8];
#pragma unroll
        for (int j = 0; j < 8; j++) {
            float f = __bfloat162float(sh[seg * 8 + j][d]) + __bfloat162float(sl[seg * 8 + j][d]);
            __half hv = __float2half_rn(f);
            th[j] = hv;
            tl[j] = __float2half_rn(f - __half2float(hv));
        }
        *(uint4*)(dh + (long)d * 2048 + seg * 8) = *(uint4*)th;
        *(uint4*)(dl + (long)d * 2048 + seg * 8) = *(uint4*)tl;
    }
}

// ---------------------------------------------------------------------------
// fused_attn: 256 threads, 64-q tile, 64-wide K tiles, 2 CTAs/SM.
// Q fragments HOISTED into registers (loaded once, reused for 64 tile passes).
// QK: bf16 3-product. PV: P fp16 x V fp16 hi/lo (2-product).
// smem unchanged from r11.
// ---------------------------------------------------------------------------
#define FQ_H  0
#define FQ_L  9216
#define FKBUF(b) (18432 + (b) * 18432)
#define FP_H  55296
#define FV_H  64512
#define FV_L  73728
#define FPART 82944
#define FINVS 83968
#define SM_FUSED 84224

__global__ __launch_bounds__(256, 2) void fused_attn(
    const bf16* __restrict__ Qh, const bf16* __restrict__ Ql,
    const bf16* __restrict__ Kh, const bf16* __restrict__ Kl,
    const __half* __restrict__ Vth, const __half* __restrict__ Vtl,
    const float* __restrict__ mask,
    float* __restrict__ A, bf16* __restrict__ Bh, bf16* __restrict__ Bl)
{
    extern __shared__ char sm[];
    uint32_t sb = smem_u32(sm);
    int t = threadIdx.x, lane = t & 31, wid = t >> 5;
    int wm = wid & 1, wn = wid >> 1;          // 2m x 4n; warp tile 32q x 16k
    int qt = blockIdx.x, bh = blockIdx.y;
    int b = bh >> 4, h = bh & 15;

    const bf16* qh = Qh + ((long)b * 2048 + qt * 64) * 1024 + h * 64;
    const bf16* ql = Ql + ((long)b * 2048 + qt * 64) * 1024 + h * 64;
    const bf16* kh = Kh + (long)b * 2048 * 1024 + h * 64;
    const bf16* kl = Kl + (long)b * 2048 * 1024 + h * 64;
    const __half* vth = Vth + (long)bh * 64 * 2048;
    const __half* vtl = Vtl + (long)bh * 64 * 2048;
    float* Abh = A + ((long)bh * 2048 + qt * 64) * 2048;
    const float* mrow = mask + (long)b * 2048;

    float* part = (float*)(sm + FPART);
    float* invs = (float*)(sm + FINVS);

#define KISSUE(kt_, buf_) do {                                                   \
    int _kt = (kt_); uint32_t _kb = sb + FKBUF(buf_);                            \
    _Pragma("unroll")                                                            \
    for (int i = 0; i < 4; i++) {                                                \
        int w = t + 256 * i;                                                     \
        int tile = w >> 9, inner = w & 511;                                      \
        int row = inner >> 3, sg = inner & 7;                                    \
        const bf16* src = (tile ? kl : kh) + (long)(_kt * 64 + row) * 1024 + sg * 8; \
        CP16(_kb + tile * 9216 + row * 144 + sg * 16, src);                      \
    }                                                                            \
    CPCOMMIT();                                                                  \
} while (0)

#define VISSUE(kt_) do {                                                         \
    int _kt = (kt_);                                                             \
    _Pragma("unroll")                                                            \
    for (int i = 0; i < 4; i++) {                                                \
        int w = t + 256 * i;                                                     \
        int tile = w >> 9, inner = w & 511;                                      \
        int row = inner >> 3, sg = inner & 7;                                    \
        const __half* src = (tile ? vtl : vth) + (long)row * 2048 + _kt * 64 + sg * 8; \
        CP16(sb + (tile ? FV_L : FV_H) + row * 144 + sg * 16, src);              \
    }                                                                            \
    CPCOMMIT();                                                                  \
} while (0)

    // prologue: K(0) async, Q tiles plain
    KISSUE(0, 0);
#pragma unroll
    for (int i = 0; i < 4; i++) {
        int w = t + 256 * i;
        int tile = w >> 9, inner = w & 511;
        int row = inner >> 3, sg = inner & 7;
        const bf16* src = (tile ? ql : qh) + (long)row * 1024 + sg * 8;
        *(uint4*)(sm + (tile ? FQ_L : FQ_H) + row * 144 + sg * 16) = *(const uint4*)src;
    }
    __syncthreads();   // Q visible to all warps

    // hoist Q fragments into registers: 2 mt x 4 k0 x 4 regs, hi + lo
    uint32_t qfh[2][4][4], qfl[2][4][4];
#pragma unroll
    for (int mt = 0; mt < 2; mt++)
#pragma unroll
        for (int k4 = 0; k4 < 4; k4++) {
            ldsmA(qfh[mt][k4], sb + FQ_H, wm * 32 + mt * 16, k4 * 16, 144, lane);
            ldsmA(qfl[mt][k4], sb + FQ_L, wm * 32 + mt * 16, k4 * 16, 144, lane);
        }

    // ---------------- pass A: rowsum only ----------------
    float rs[4] = {0.f, 0.f, 0.f, 0.f};
    for (int kt = 0; kt < 32; kt++) {
        CPWAIT(0);
        __syncthreads();
        if (kt + 1 < 32) KISSUE(kt + 1, (kt + 1) & 1);

        uint32_t kb = sb + FKBUF(kt & 1);
        float acc[2][2][4] = {};
#pragma unroll
        for (int k4 = 0; k4 < 4; k4++) {
            uint32_t bhf[4], blf[4];
            ldsmB(bhf, kb,        wn * 16, k4 * 16, 144, lane);
            ldsmB(blf, kb + 9216, wn * 16, k4 * 16, 144, lane);
#pragma unroll
            for (int mt = 0; mt < 2; mt++) {
                mma3(acc[mt][0], qfh[mt][k4], qfl[mt][k4], &bhf[0], &blf[0]);
                mma3(acc[mt][1], qfh[mt][k4], qfl[mt][k4], &bhf[2], &blf[2]);
            }
        }
#pragma unroll
        for (int nt = 0; nt < 2; nt++) {
            int cl = kt * 64 + wn * 16 + nt * 8 + 2 * (lane & 3);
            float m0v = (1.0f - mrow[cl]) * (-1e9f);
            float m1v = (1.0f - mrow[cl + 1]) * (-1e9f);
#pragma unroll
            for (int mt = 0; mt < 2; mt++) {
                float* cc = acc[mt][nt];
                rs[mt * 2 + 0] += __expf(cc[0] + m0v) + __expf(cc[1] + m1v);
                rs[mt * 2 + 1] += __expf(cc[2] + m0v) + __expf(cc[3] + m1v);
            }
        }
    }

    KISSUE(0, 0);     // K(0) for pass B

    // reduce rowsum -> invs[64]
#pragma unroll
    for (int i = 0; i < 4; i++) {
        rs[i] += __shfl_xor_sync(0xffffffffu, rs[i], 1);
        rs[i] += __shfl_xor_sync(0xffffffffu, rs[i], 2);
    }
    __syncthreads();
    if ((lane & 3) == 0) {
#pragma unroll
        for (int mt = 0; mt < 2; mt++)
#pragma unroll
            for (int hf = 0; hf < 2; hf++)
                part[wn * 64 + wm * 32 + mt * 16 + hf * 8 + (lane >> 2)] = rs[mt * 2 + hf];
    }
    __syncthreads();
    if (t < 64)
        invs[t] = 1.0f / (part[t] + part[64 + t] + part[128 + t] + part[192 + t]);
    __syncthreads();

    float invr[2][2];
#pragma unroll
    for (int mt = 0; mt < 2; mt++) {
        invr[mt][0] = invs[wm * 32 + mt * 16 + (lane >> 2)];
        invr[mt][1] = invs[wm * 32 + mt * 16 + 8 + (lane >> 2)];
    }

    // ---------------- pass B ----------------
    float oacc[2][2][4] = {};
    for (int kt = 0; kt < 32; kt++) {
        CPWAIT(0);
        __syncthreads();                   // K(kt) ready; prior P/V reads done
        VISSUE(kt);                        // V first (released by wait_group 1)
        if (kt + 1 < 32) KISSUE(kt + 1, (kt + 1) & 1);

        uint32_t kb = sb + FKBUF(kt & 1);
        float acc[2][2][4] = {};
#pragma unroll
        for (int k4 = 0; k4 < 4; k4++) {
            uint32_t bhf[4], blf[4];
            ldsmB(bhf, kb,        wn * 16, k4 * 16, 144, lane);
            ldsmB(blf, kb + 9216, wn * 16, k4 * 16, 144, lane);
#pragma unroll
            for (int mt = 0; mt < 2; mt++) {
                mma3(acc[mt][0], qfh[mt][k4], qfl[mt][k4], &bhf[0], &blf[0]);
                mma3(acc[mt][1], qfh[mt][k4], qfl[mt][k4], &bhf[2], &blf[2]);
            }
        }

        // epilogue: normalize, write attn (fp32 exact), pack P fp16 -> smem
#pragma unroll
        for (int nt = 0; nt < 2; nt++) {
            int cl = wn * 16 + nt * 8 + 2 * (lane & 3);
            int gc = kt * 64 + cl;
            float m0v = (1.0f - mrow[gc]) * (-1e9f);
            float m1v = (1.0f - mrow[gc + 1]) * (-1e9f);
#pragma unroll
            for (int mt = 0; mt < 2; mt++) {
                float* cc = acc[mt][nt];
                int r0 = wm * 32 + mt * 16 + (lane >> 2);
                float e0 = __expf(cc[0] + m0v) * invr[mt][0];
                float e1 = __expf(cc[1] + m1v) * invr[mt][0];
                float e2 = __expf(cc[2] + m0v) * invr[mt][1];
                float e3 = __expf(cc[3] + m1v) * invr[mt][1];
                *(float2*)(Abh + (long)r0 * 2048 + gc)       = make_float2(e0, e1);
                *(float2*)(Abh + (long)(r0 + 8) * 2048 + gc) = make_float2(e2, e3);
                smem_h2f16(sm + FP_H + r0 * 144 + cl * 2, e0, e1);
                smem_h2f16(sm + FP_H + (r0 + 8) * 144 + cl * 2, e2, e3);
            }
        }

        if (kt + 1 < 32) { CPWAIT(1); } else { CPWAIT(0); }
        __syncthreads();                   // V(kt) + P visible

        // O += P(fp16) · (Vh + Vl)^T
#pragma unroll
        for (int k4 = 0; k4 < 4; k4++) {
            uint32_t ah[2][4], bhf[4], blf[4];
#pragma unroll
            for (int mt = 0; mt < 2; mt++)
                ldsmA(ah[mt], sb + FP_H, wm * 32 + mt * 16, k4 * 16, 144, lane);
            ldsmB(bhf, sb + FV_H, wn * 16, k4 * 16, 144, lane);
            ldsmB(blf, sb + FV_L, wn * 16, k4 * 16, 144, lane);
#pragma unroll
            for (int mt = 0; mt < 2; mt++) {
                mma16816h(oacc[mt][0], ah[mt], &bhf[0]);
                mma16816h(oacc[mt][0], ah[mt], &blf[0]);
                mma16816h(oacc[mt][1], ah[mt], &bhf[2]);
                mma16816h(oacc[mt][1], ah[mt], &blf[2]);
            }
        }
    }

    // write blended split [b, q, h*64+d]
#pragma unroll
    for (int mt = 0; mt < 2; mt++)
#pragma unroll
        for (int nt = 0; nt < 2; nt++) {
            float* cc = oacc[mt][nt];
            long r0 = (long)b * 2048 + qt * 64 + wm * 32 + mt * 16 + (lane >> 2);
            int col = h * 64 + wn * 16 + nt * 8 + 2 * (lane & 3);
            store_split2(Bh, Bl, r0 * 1024 + col, cc[0], cc[1]);
            store_split2(Bh, Bl, (r0 + 8) * 1024 + col, cc[2], cc[3]);
        }
}

// ===========================================================================
extern "C" void kernel_launch(void* const* d_in, const int* in_sizes, int n_in,
                              void* d_out, int out_size) {
    (void)in_sizes; (void)n_in;
    const float* query        = (const float*)d_in[0];
    const float* input_embeds = (const float*)d_in[1];
    const float* mask         = (const float*)d_in[2];
    const float* wq_w = (const float*)d_in[3];
    const float* wq_b = (const float*)d_in[4];
    const float* wk_w = (const float*)d_in[5];
    const float* wk_b = (const float*)d_in[6];
    const float* wv_w = (const float*)d_in[7];
    const float* wv_b = (const float*)d_in[8];
    const float* wo_w = (const float*)d_in[9];
    const float* wo_b = (const float*)d_in[10];
    float* out = (float*)d_out;

    bf16 *qh, *ql, *xh, *xl, *wqh, *wql, *wkh, *wkl, *wvh, *wvl, *woh, *wol;
    bf16 *Qh, *Ql, *Kh, *Kl, *Vh, *Vl, *Bh, *Bl;
    __half *Vth16, *Vtl16;
    float *attn_scratch;
    cudaGetSymbolAddress((void**)&qh, g_qh);   cudaGetSymbolAddress((void**)&ql, g_ql);
    cudaGetSymbolAddress((void**)&xh, g_xh);   cudaGetSymbolAddress((void**)&xl, g_xl);
    cudaGetSymbolAddress((void**)&wqh, g_wqh); cudaGetSymbolAddress((void**)&wql, g_wql);
    cudaGetSymbolAddress((void**)&wkh, g_wkh); cudaGetSymbolAddress((void**)&wkl, g_wkl);
    cudaGetSymbolAddress((void**)&wvh, g_wvh); cudaGetSymbolAddress((void**)&wvl, g_wvl);
    cudaGetSymbolAddress((void**)&woh, g_woh); cudaGetSymbolAddress((void**)&wol, g_wol);
    cudaGetSymbolAddress((void**)&Qh, g_Qh);   cudaGetSymbolAddress((void**)&Ql, g_Ql);
    cudaGetSymbolAddress((void**)&Kh, g_Kh);   cudaGetSymbolAddress((void**)&Kl, g_Kl);
    cudaGetSymbolAddress((void**)&Vh, g_Vh);   cudaGetSymbolAddress((void**)&Vl, g_Vl);
    cudaGetSymbolAddress((void**)&Vth16, g_Vth16);
    cudaGetSymbolAddress((void**)&Vtl16, g_Vtl16);
    cudaGetSymbolAddress((void**)&Bh, g_Bh);   cudaGetSymbolAddress((void**)&Bl, g_Bl);
    cudaGetSymbolAddress((void**)&attn_scratch, g_attn);

    const long OUT_E = 4194304L, ATTN_E = 134217728L;
    float* attn = ((long)out_size >= OUT_E + ATTN_E) ? (out + OUT_E) : attn_scratch;

    const int SM_GEMM = 81920;
    cudaFuncSetAttribute(proj3,      cudaFuncAttributeMaxDynamicSharedMemorySize, SM_GEMM);
    cudaFuncSetAttribute(hgemm_out,  cudaFuncAttributeMaxDynamicSharedMemorySize, SM_GEMM);
    cudaFuncSetAttribute(fused_attn, cudaFuncAttributeMaxDynamicSharedMemorySize, SM_FUSED);

    cvt_all<<<12288, 256>>>(query, input_embeds, wq_w, wk_w, wv_w, wo_w,
                            qh, ql, xh, xl, wqh, wql, wkh, wkl, wvh, wvl, woh, wol);

    proj3<<<dim3(8, 32, 3), 256, SM_GEMM>>>(qh, ql, xh, xl,
                                            wqh, wql, wkh, wkl, wvh, wvl,
                                            wq_b, wk_b, wv_b,
                                            Qh, Ql, Kh, Kl, Vh, Vl);

    vtrans<<<dim3(32, 32), 256>>>(Vh, Vl, Vth16, Vtl16);

    fused_attn<<<dim3(32, 32), 256, SM_FUSED>>>(Qh, Ql, Kh, Kl, Vth16, Vtl16, mask,
                                                attn, Bh, Bl);

    hgemm_out<<<dim3(8, 32), 256, SM_GEMM>>>(Bh, Bl, woh, wol, wo_b, out);
}